// round 6
// baseline (speedup 1.0000x reference)
#include <cuda_runtime.h>
#include <cuda_bf16.h>
#include <cstdint>

#define NN 100000
#define NE 1600000
#define CIN 128
#define NBLK ((NN + 255) / 256)   // 391 scan blocks

// ---------------- scratch ---------------------------------------------------
static __device__ int   g_deg[NN];
static __device__ int   g_cur[NN];
static __device__ float g_dis[NN];
static __device__ int   g_off[NN + 1];
static __device__ int   g_bsum[512];
static __device__ int   g_bscan[512];
static __device__ int   g_ep[NE];                 // src per (dst-sorted) edge
static __device__ float g_h[(size_t)NN * 128];    // dis-scaled transform output
static __device__ float g_a[(size_t)NN * 128];    // aggregation buffer
// pre-transposed + bf16 hi/lo split weights: [COUT][CIN] bf16
static __device__ __nv_bfloat16 g_w1h[128 * 128], g_w1l[128 * 128];
static __device__ __nv_bfloat16 g_w2h[128 * 128], g_w2l[128 * 128];
static __device__ __nv_bfloat16 g_w3h[64 * 128],  g_w3l[64 * 128];

// ---------------- PTX helpers ------------------------------------------------
__device__ __forceinline__ uint32_t smem_u32(const void* p) {
    uint32_t a;
    asm("{ .reg .u64 t; cvta.to.shared.u64 t, %1; cvt.u32.u64 %0, t; }" : "=r"(a) : "l"(p));
    return a;
}
__device__ __forceinline__ void ldsm4(uint32_t* r, uint32_t addr) {
    asm volatile("ldmatrix.sync.aligned.m8n8.x4.shared.b16 {%0,%1,%2,%3}, [%4];"
                 : "=r"(r[0]), "=r"(r[1]), "=r"(r[2]), "=r"(r[3]) : "r"(addr));
}
__device__ __forceinline__ void mma16816(float* d, const uint32_t* a,
                                         uint32_t b0, uint32_t b1) {
    asm volatile(
        "mma.sync.aligned.m16n8k16.row.col.f32.bf16.bf16.f32 "
        "{%0,%1,%2,%3}, {%4,%5,%6,%7}, {%8,%9}, {%0,%1,%2,%3};"
        : "+f"(d[0]), "+f"(d[1]), "+f"(d[2]), "+f"(d[3])
        : "r"(a[0]), "r"(a[1]), "r"(a[2]), "r"(a[3]), "r"(b0), "r"(b1));
}

// ---------------- init: self-loop degree + weight transpose/split ------------
__global__ void k_init(const float* __restrict__ W1, const float* __restrict__ W2,
                       const float* __restrict__ W3) {
    int i = blockIdx.x * blockDim.x + threadIdx.x;
    if (i < NN) g_deg[i] = 1;                       // self loop
    if (i < 16384) {
        int k = i >> 7, n = i & 127;
        float v = W1[i];
        __nv_bfloat16 hi = __float2bfloat16_rn(v);
        g_w1h[n * 128 + k] = hi;
        g_w1l[n * 128 + k] = __float2bfloat16_rn(v - __bfloat162float(hi));
        v = W2[i]; hi = __float2bfloat16_rn(v);
        g_w2h[n * 128 + k] = hi;
        g_w2l[n * 128 + k] = __float2bfloat16_rn(v - __bfloat162float(hi));
    }
    if (i < 8192) {
        int k = i >> 6, n = i & 63;
        float v = W3[i];
        __nv_bfloat16 hi = __float2bfloat16_rn(v);
        g_w3h[n * 128 + k] = hi;
        g_w3l[n * 128 + k] = __float2bfloat16_rn(v - __bfloat162float(hi));
    }
}
__global__ void k_deg_count(const int* __restrict__ dst) {
    int e = blockIdx.x * blockDim.x + threadIdx.x;
    if (e < NE) atomicAdd(&g_deg[dst[e]], 1);
}

// ---------------- CSR build (dis fused into scan1) ---------------------------
__global__ void k_scan1() {
    __shared__ int s[256];
    int t = threadIdx.x;
    int i = blockIdx.x * 256 + t;
    int deg = (i < NN) ? g_deg[i] : 1;
    if (i < NN) g_dis[i] = rsqrtf((float)deg);
    int v = (i < NN) ? (deg - 1) : 0;
    s[t] = v; __syncthreads();
#pragma unroll
    for (int off = 1; off < 256; off <<= 1) {
        int a = (t >= off) ? s[t - off] : 0;
        __syncthreads();
        s[t] += a; __syncthreads();
    }
    if (i < NN) g_off[i] = s[t] - v;
    if (t == 255) g_bsum[blockIdx.x] = s[255];
}
__global__ void k_scan2() {
    __shared__ int s[512];
    int t = threadIdx.x;
    int v = (t < NBLK) ? g_bsum[t] : 0;
    s[t] = v; __syncthreads();
#pragma unroll
    for (int off = 1; off < 512; off <<= 1) {
        int a = (t >= off) ? s[t - off] : 0;
        __syncthreads();
        s[t] += a; __syncthreads();
    }
    g_bscan[t] = s[t] - v;
}
__global__ void k_scan3() {
    int i = blockIdx.x * blockDim.x + threadIdx.x;
    if (i < NN) {
        int o = g_off[i] + g_bscan[i >> 8];
        g_off[i] = o;
        g_cur[i] = o;
    }
    if (i == 0) g_off[NN] = NE;
}
__global__ void k_fill(const int* __restrict__ src, const int* __restrict__ dst) {
    int e = blockIdx.x * blockDim.x + threadIdx.x;
    if (e >= NE) return;
    int pos = atomicAdd(&g_cur[dst[e]], 1);
    g_ep[pos] = src[e];
}

// ---------------- bf16-split tensor-core GEMM: h' = dis * (f(in) @ W) --------
// D = Ah*Bh + Al*Bh + Ah*Bl (fp32 accum). 128-row tiles, K chunked by 64.
// smem rows padded to 72 bf16 (144 B) -> conflict-free ldmatrix.
// 8 warps = 4(M) x 2(N).
template <int COUT, bool RELU_IN>
__global__ void __launch_bounds__(256)
k_gemm_mma(const float* __restrict__ in, const __nv_bfloat16* __restrict__ wh,
           const __nv_bfloat16* __restrict__ wl, const float* __restrict__ bin,
           float* __restrict__ h)
{
    constexpr int PITCH = 144;                 // bytes per smem row (72 bf16)
    constexpr int ASZ = 128 * PITCH;           // 18432
    constexpr int BSZ = COUT * PITCH;
    constexpr int NTW = COUT / 16;             // n8 tiles per warp (8 or 4)

    extern __shared__ char smem[];
    char* Ah = smem;
    char* Al = smem + ASZ;
    char* Bh = smem + 2 * ASZ;
    char* Bl = Bh + BSZ;
    uint32_t sb = smem_u32(smem);

    int tid = threadIdx.x;
    int wid = tid >> 5, lane = tid & 31;
    int wm = wid >> 1, wn = wid & 1;
    int row0 = blockIdx.x * 128;

    float acc[2][NTW][4];
#pragma unroll
    for (int f = 0; f < 2; f++)
#pragma unroll
        for (int t = 0; t < NTW; t++)
#pragma unroll
            for (int q = 0; q < 4; q++) acc[f][t][q] = 0.f;

    // per-lane ldmatrix address components
    uint32_t lrow = lane & 7, quad = lane >> 3;
    uint32_t aoff = sb +
                    (wm * 32 + lrow + ((quad & 1) << 3)) * PITCH + ((quad & 2) << 3);
    uint32_t boff = sb + (uint32_t)(2 * ASZ) +
                    (wn * (COUT / 2) + lrow + ((quad & 2) << 2)) * PITCH + ((quad & 1) << 4);

    for (int c = 0; c < 2; c++) {
        // ---- stage A chunk [128 x 64] fp32 -> bf16 hi/lo -------------------
        {
            int r = tid >> 1, half = tid & 1;
            int gr = row0 + r;
            const float* ip = in + (size_t)gr * CIN + c * 64 + half * 32;
            __nv_bfloat162* arh = reinterpret_cast<__nv_bfloat162*>(Ah + r * PITCH + half * 64);
            __nv_bfloat162* arl = reinterpret_cast<__nv_bfloat162*>(Al + r * PITCH + half * 64);
#pragma unroll
            for (int q = 0; q < 8; q++) {
                float4 v = make_float4(0.f, 0.f, 0.f, 0.f);
                if (gr < NN) v = *reinterpret_cast<const float4*>(ip + q * 4);
                if (RELU_IN) {
                    float4 b = *reinterpret_cast<const float4*>(bin + c * 64 + half * 32 + q * 4);
                    v.x = fmaxf(v.x + b.x, 0.f); v.y = fmaxf(v.y + b.y, 0.f);
                    v.z = fmaxf(v.z + b.z, 0.f); v.w = fmaxf(v.w + b.w, 0.f);
                }
                __nv_bfloat162 h0, h1, l0, l1;
                h0.x = __float2bfloat16_rn(v.x); h0.y = __float2bfloat16_rn(v.y);
                h1.x = __float2bfloat16_rn(v.z); h1.y = __float2bfloat16_rn(v.w);
                l0.x = __float2bfloat16_rn(v.x - __bfloat162float(h0.x));
                l0.y = __float2bfloat16_rn(v.y - __bfloat162float(h0.y));
                l1.x = __float2bfloat16_rn(v.z - __bfloat162float(h1.x));
                l1.y = __float2bfloat16_rn(v.w - __bfloat162float(h1.y));
                arh[q * 2] = h0; arh[q * 2 + 1] = h1;
                arl[q * 2] = l0; arl[q * 2 + 1] = l1;
            }
        }
        // ---- stage B chunk [COUT x 64] bf16 copy ---------------------------
        {
            constexpr int TPR = 256 / COUT;    // 2 or 4
            constexpr int VPT = 8 / TPR;       // uint4 per thread: 4 or 2
            int n = tid / TPR, part = tid % TPR;
            const uint4* sh = reinterpret_cast<const uint4*>(wh + n * 128 + c * 64) + part * VPT;
            const uint4* sl = reinterpret_cast<const uint4*>(wl + n * 128 + c * 64) + part * VPT;
            uint4* dh = reinterpret_cast<uint4*>(Bh + n * PITCH) + part * VPT;
            uint4* dl = reinterpret_cast<uint4*>(Bl + n * PITCH) + part * VPT;
#pragma unroll
            for (int v = 0; v < VPT; v++) { dh[v] = sh[v]; dl[v] = sl[v]; }
        }
        __syncthreads();

        // ---- compute: 4 k16 steps ------------------------------------------
#pragma unroll
        for (int kk = 0; kk < 4; kk++) {
            uint32_t ka = (uint32_t)(kk << 5);
            uint32_t afr[2][4], afl[2][4];
            ldsm4(afr[0], aoff + ka);
            ldsm4(afr[1], aoff + 16 * PITCH + ka);
            ldsm4(afl[0], aoff + ASZ + ka);
            ldsm4(afl[1], aoff + ASZ + 16 * PITCH + ka);
#pragma unroll
            for (int tp = 0; tp < NTW / 2; tp++) {
                uint32_t bfr[4], bfl[4];
                ldsm4(bfr, boff + tp * 16 * PITCH + ka);
                ldsm4(bfl, boff + BSZ + tp * 16 * PITCH + ka);
#pragma unroll
                for (int f = 0; f < 2; f++) {
                    mma16816(acc[f][2 * tp],     afr[f], bfr[0], bfr[1]);
                    mma16816(acc[f][2 * tp],     afl[f], bfr[0], bfr[1]);
                    mma16816(acc[f][2 * tp],     afr[f], bfl[0], bfl[1]);
                    mma16816(acc[f][2 * tp + 1], afr[f], bfr[2], bfr[3]);
                    mma16816(acc[f][2 * tp + 1], afl[f], bfr[2], bfr[3]);
                    mma16816(acc[f][2 * tp + 1], afr[f], bfl[2], bfl[3]);
                }
            }
        }
        __syncthreads();
    }

    // ---- epilogue: scale by dis, store h' -----------------------------------
#pragma unroll
    for (int f = 0; f < 2; f++) {
        int r0g = row0 + wm * 32 + f * 16 + (lane >> 2);
        float ds0 = (r0g < NN) ? g_dis[r0g] : 0.f;
        float ds1 = (r0g + 8 < NN) ? g_dis[r0g + 8] : 0.f;
#pragma unroll
        for (int t = 0; t < NTW; t++) {
            int ncol = wn * (COUT / 2) + t * 8 + ((lane & 3) << 1);
            if (r0g < NN) {
                float2 o = make_float2(acc[f][t][0] * ds0, acc[f][t][1] * ds0);
                *reinterpret_cast<float2*>(h + (size_t)r0g * COUT + ncol) = o;
            }
            if (r0g + 8 < NN) {
                float2 o = make_float2(acc[f][t][2] * ds1, acc[f][t][3] * ds1);
                *reinterpret_cast<float2*>(h + (size_t)(r0g + 8) * COUT + ncol) = o;
            }
        }
    }
}

// ---------------- gather: agg[d] = dis[d]*(sum_src h'[src] + h'[d]) ----------
__global__ void k_gather128(const float* __restrict__ h, float* __restrict__ agg)
{
    int warp = (blockIdx.x * blockDim.x + threadIdx.x) >> 5;
    int lane = threadIdx.x & 31;
    if (warp >= NN) return;
    int beg = g_off[warp], end = g_off[warp + 1];
    const float4* hp = reinterpret_cast<const float4*>(h);
    float4 acc = hp[warp * 32 + lane];                 // self term
    int i = beg;
    for (; i + 8 <= end; i += 8) {
        float4 v0 = hp[g_ep[i    ] * 32 + lane];
        float4 v1 = hp[g_ep[i + 1] * 32 + lane];
        float4 v2 = hp[g_ep[i + 2] * 32 + lane];
        float4 v3 = hp[g_ep[i + 3] * 32 + lane];
        float4 v4 = hp[g_ep[i + 4] * 32 + lane];
        float4 v5 = hp[g_ep[i + 5] * 32 + lane];
        float4 v6 = hp[g_ep[i + 6] * 32 + lane];
        float4 v7 = hp[g_ep[i + 7] * 32 + lane];
        acc.x += ((v0.x + v1.x) + (v2.x + v3.x)) + ((v4.x + v5.x) + (v6.x + v7.x));
        acc.y += ((v0.y + v1.y) + (v2.y + v3.y)) + ((v4.y + v5.y) + (v6.y + v7.y));
        acc.z += ((v0.z + v1.z) + (v2.z + v3.z)) + ((v4.z + v5.z) + (v6.z + v7.z));
        acc.w += ((v0.w + v1.w) + (v2.w + v3.w)) + ((v4.w + v5.w) + (v6.w + v7.w));
    }
    for (; i < end; i++) {
        float4 v = hp[g_ep[i] * 32 + lane];
        acc.x += v.x; acc.y += v.y; acc.z += v.z; acc.w += v.w;
    }
    float dd = g_dis[warp];
    acc.x *= dd; acc.y *= dd; acc.z *= dd; acc.w *= dd;
    reinterpret_cast<float4*>(agg)[warp * 32 + lane] = acc;
}

__global__ void k_gather64f(const float* __restrict__ h, const float* __restrict__ b3,
                            float* __restrict__ out)
{
    int warp = (blockIdx.x * blockDim.x + threadIdx.x) >> 5;
    int lane = threadIdx.x & 31;
    if (warp >= NN) return;
    int beg = g_off[warp], end = g_off[warp + 1];
    const float2* hp = reinterpret_cast<const float2*>(h);
    float2 acc = hp[warp * 32 + lane];                 // self term
    int i = beg;
    for (; i + 8 <= end; i += 8) {
        float2 v0 = hp[g_ep[i    ] * 32 + lane];
        float2 v1 = hp[g_ep[i + 1] * 32 + lane];
        float2 v2 = hp[g_ep[i + 2] * 32 + lane];
        float2 v3 = hp[g_ep[i + 3] * 32 + lane];
        float2 v4 = hp[g_ep[i + 4] * 32 + lane];
        float2 v5 = hp[g_ep[i + 5] * 32 + lane];
        float2 v6 = hp[g_ep[i + 6] * 32 + lane];
        float2 v7 = hp[g_ep[i + 7] * 32 + lane];
        acc.x += ((v0.x + v1.x) + (v2.x + v3.x)) + ((v4.x + v5.x) + (v6.x + v7.x));
        acc.y += ((v0.y + v1.y) + (v2.y + v3.y)) + ((v4.y + v5.y) + (v6.y + v7.y));
    }
    for (; i < end; i++) {
        float2 v = hp[g_ep[i] * 32 + lane];
        acc.x += v.x; acc.y += v.y;
    }
    float dd = g_dis[warp];
    float2 b = reinterpret_cast<const float2*>(b3)[lane];
    float2 r;
    r.x = fmaf(acc.x, dd, b.x);
    r.y = fmaf(acc.y, dd, b.y);
    reinterpret_cast<float2*>(out)[warp * 32 + lane] = r;
}

// ---------------- launcher ---------------------------------------------------
extern "C" void kernel_launch(void* const* d_in, const int* in_sizes, int n_in,
                              void* d_out, int out_size)
{
    const float* x  = (const float*)d_in[0];
    const int*   ei = (const int*)d_in[1];
    const float* W1 = (const float*)d_in[2];
    const float* b1 = (const float*)d_in[3];
    const float* W2 = (const float*)d_in[4];
    const float* b2 = (const float*)d_in[5];
    const float* W3 = (const float*)d_in[6];
    const float* b3 = (const float*)d_in[7];
    float* out = (float*)d_out;

    const int* src = ei;            // edge_index[0]
    const int* dst = ei + NE;       // edge_index[1]

    float *ph = nullptr, *pa = nullptr;
    cudaGetSymbolAddress((void**)&ph, g_h);
    cudaGetSymbolAddress((void**)&pa, g_a);
    __nv_bfloat16 *w1h, *w1l, *w2h, *w2l, *w3h, *w3l;
    cudaGetSymbolAddress((void**)&w1h, g_w1h);
    cudaGetSymbolAddress((void**)&w1l, g_w1l);
    cudaGetSymbolAddress((void**)&w2h, g_w2h);
    cudaGetSymbolAddress((void**)&w2l, g_w2l);
    cudaGetSymbolAddress((void**)&w3h, g_w3h);
    cudaGetSymbolAddress((void**)&w3l, g_w3l);

    const int smem128 = 2 * 128 * 144 + 2 * 128 * 144;   // 73728
    const int smem64  = 2 * 128 * 144 + 2 * 64 * 144;    // 55296
    cudaFuncSetAttribute(k_gemm_mma<128, false>, cudaFuncAttributeMaxDynamicSharedMemorySize, smem128);
    cudaFuncSetAttribute(k_gemm_mma<128, true>,  cudaFuncAttributeMaxDynamicSharedMemorySize, smem128);
    cudaFuncSetAttribute(k_gemm_mma<64,  true>,  cudaFuncAttributeMaxDynamicSharedMemorySize, smem64);

    const int gB = (NN + 127) / 128;         // 782 M-tiles
    const int gG = (NN * 32 + 255) / 256;    // warp per node

    // setup (5 launches) — gemm1 is launch #6 so ncu -s 5 -c 1 profiles it
    k_init<<<NBLK, 256>>>(W1, W2, W3);                       // 1
    k_deg_count<<<(NE + 255) / 256, 256>>>(dst);             // 2
    k_scan1<<<NBLK, 256>>>();                                // 3 (dis fused)
    k_scan2<<<1, 512>>>();                                   // 4
    k_scan3<<<NBLK, 256>>>();                                // 5

    // layer 1 (gemm first; CSR fill runs after, before the gather needs it)
    k_gemm_mma<128, false><<<gB, 256, smem128>>>(x, w1h, w1l, b1, ph);  // 6
    k_fill<<<(NE + 255) / 256, 256>>>(src, dst);             // 7
    k_gather128<<<gG, 256>>>(ph, pa);                        // 8
    // layer 2
    k_gemm_mma<128, true><<<gB, 256, smem128>>>(pa, w2h, w2l, b1, ph);  // 9
    k_gather128<<<gG, 256>>>(ph, pa);                        // 10
    // layer 3 (COUT=64) + fused final bias
    k_gemm_mma<64, true><<<gB, 256, smem64>>>(pa, w3h, w3l, b2, ph);    // 11
    k_gather64f<<<gG, 256>>>(ph, b3, out);                   // 12
}

// round 7
// speedup vs baseline: 1.1322x; 1.1322x over previous
#include <cuda_runtime.h>
#include <cuda_bf16.h>
#include <cuda_fp16.h>
#include <cstdint>

#define NN 100000
#define NE 1600000
#define CIN 128
#define NBLK ((NN + 255) / 256)   // 391 scan blocks

// ---------------- scratch ---------------------------------------------------
static __device__ int    g_deg[NN];
static __device__ int    g_cur[NN];
static __device__ float  g_dis[NN];
static __device__ int    g_off[NN + 1];
static __device__ int    g_bsum[512];
static __device__ int    g_bscan[512];
static __device__ int    g_ep[NE];                 // src per (dst-sorted) edge
static __device__ __half g_h[(size_t)NN * 128];    // dis-scaled messages (fp16)
static __device__ float  g_a[(size_t)NN * 128];    // aggregation buffer (fp32)
// pre-transposed + bf16 hi/lo split weights: [COUT][CIN] bf16
static __device__ __nv_bfloat16 g_w1h[128 * 128], g_w1l[128 * 128];
static __device__ __nv_bfloat16 g_w2h[128 * 128], g_w2l[128 * 128];
static __device__ __nv_bfloat16 g_w3h[64 * 128],  g_w3l[64 * 128];

// ---------------- PTX helpers ------------------------------------------------
__device__ __forceinline__ uint32_t smem_u32(const void* p) {
    uint32_t a;
    asm("{ .reg .u64 t; cvta.to.shared.u64 t, %1; cvt.u32.u64 %0, t; }" : "=r"(a) : "l"(p));
    return a;
}
__device__ __forceinline__ void ldsm4(uint32_t* r, uint32_t addr) {
    asm volatile("ldmatrix.sync.aligned.m8n8.x4.shared.b16 {%0,%1,%2,%3}, [%4];"
                 : "=r"(r[0]), "=r"(r[1]), "=r"(r[2]), "=r"(r[3]) : "r"(addr));
}
__device__ __forceinline__ void mma16816(float* d, const uint32_t* a,
                                         uint32_t b0, uint32_t b1) {
    asm volatile(
        "mma.sync.aligned.m16n8k16.row.col.f32.bf16.bf16.f32 "
        "{%0,%1,%2,%3}, {%4,%5,%6,%7}, {%8,%9}, {%0,%1,%2,%3};"
        : "+f"(d[0]), "+f"(d[1]), "+f"(d[2]), "+f"(d[3])
        : "r"(a[0]), "r"(a[1]), "r"(a[2]), "r"(a[3]), "r"(b0), "r"(b1));
}
__device__ __forceinline__ float4 h4_to_f4(uint2 u) {
    float2 a = __half22float2(*reinterpret_cast<__half2*>(&u.x));
    float2 b = __half22float2(*reinterpret_cast<__half2*>(&u.y));
    return make_float4(a.x, a.y, b.x, b.y);
}

// ---------------- init: self-loop degree + weight transpose/split ------------
__global__ void k_init(const float* __restrict__ W1, const float* __restrict__ W2,
                       const float* __restrict__ W3) {
    int i = blockIdx.x * blockDim.x + threadIdx.x;
    if (i < NN) g_deg[i] = 1;                       // self loop
    if (i < 16384) {
        int k = i >> 7, n = i & 127;
        float v = W1[i];
        __nv_bfloat16 hi = __float2bfloat16_rn(v);
        g_w1h[n * 128 + k] = hi;
        g_w1l[n * 128 + k] = __float2bfloat16_rn(v - __bfloat162float(hi));
        v = W2[i]; hi = __float2bfloat16_rn(v);
        g_w2h[n * 128 + k] = hi;
        g_w2l[n * 128 + k] = __float2bfloat16_rn(v - __bfloat162float(hi));
    }
    if (i < 8192) {
        int k = i >> 6, n = i & 63;
        float v = W3[i];
        __nv_bfloat16 hi = __float2bfloat16_rn(v);
        g_w3h[n * 128 + k] = hi;
        g_w3l[n * 128 + k] = __float2bfloat16_rn(v - __bfloat162float(hi));
    }
}
__global__ void k_deg_count(const int* __restrict__ dst) {
    int e = blockIdx.x * blockDim.x + threadIdx.x;
    if (e < NE) atomicAdd(&g_deg[dst[e]], 1);
}

// ---------------- CSR build (dis fused into scan1) ---------------------------
__global__ void k_scan1() {
    __shared__ int s[256];
    int t = threadIdx.x;
    int i = blockIdx.x * 256 + t;
    int deg = (i < NN) ? g_deg[i] : 1;
    if (i < NN) g_dis[i] = rsqrtf((float)deg);
    int v = (i < NN) ? (deg - 1) : 0;
    s[t] = v; __syncthreads();
#pragma unroll
    for (int off = 1; off < 256; off <<= 1) {
        int a = (t >= off) ? s[t - off] : 0;
        __syncthreads();
        s[t] += a; __syncthreads();
    }
    if (i < NN) g_off[i] = s[t] - v;
    if (t == 255) g_bsum[blockIdx.x] = s[255];
}
__global__ void k_scan2() {
    __shared__ int s[512];
    int t = threadIdx.x;
    int v = (t < NBLK) ? g_bsum[t] : 0;
    s[t] = v; __syncthreads();
#pragma unroll
    for (int off = 1; off < 512; off <<= 1) {
        int a = (t >= off) ? s[t - off] : 0;
        __syncthreads();
        s[t] += a; __syncthreads();
    }
    g_bscan[t] = s[t] - v;
}
__global__ void k_scan3() {
    int i = blockIdx.x * blockDim.x + threadIdx.x;
    if (i < NN) {
        int o = g_off[i] + g_bscan[i >> 8];
        g_off[i] = o;
        g_cur[i] = o;
    }
    if (i == 0) g_off[NN] = NE;
}
__global__ void k_fill(const int* __restrict__ src, const int* __restrict__ dst) {
    int e = blockIdx.x * blockDim.x + threadIdx.x;
    if (e >= NE) return;
    int pos = atomicAdd(&g_cur[dst[e]], 1);
    g_ep[pos] = src[e];
}

// ---------------- bf16-split tensor-core GEMM: h' = fp16(dis * (f(in) @ W)) --
// D = Ah*Bh + Al*Bh + Ah*Bl (fp32 accum). 128-row tiles, K chunked by 64.
// smem rows padded to 72 bf16 (144 B) -> conflict-free ldmatrix.
// 8 warps = 4(M) x 2(N).
template <int COUT, bool RELU_IN>
__global__ void __launch_bounds__(256)
k_gemm_mma(const float* __restrict__ in, const __nv_bfloat16* __restrict__ wh,
           const __nv_bfloat16* __restrict__ wl, const float* __restrict__ bin,
           __half* __restrict__ h)
{
    constexpr int PITCH = 144;                 // bytes per smem row (72 bf16)
    constexpr int ASZ = 128 * PITCH;           // 18432
    constexpr int BSZ = COUT * PITCH;
    constexpr int NTW = COUT / 16;             // n8 tiles per warp (8 or 4)

    extern __shared__ char smem[];
    char* Ah = smem;
    char* Al = smem + ASZ;
    char* Bh = smem + 2 * ASZ;
    char* Bl = Bh + BSZ;
    uint32_t sb = smem_u32(smem);

    int tid = threadIdx.x;
    int wid = tid >> 5, lane = tid & 31;
    int wm = wid >> 1, wn = wid & 1;
    int row0 = blockIdx.x * 128;

    float acc[2][NTW][4];
#pragma unroll
    for (int f = 0; f < 2; f++)
#pragma unroll
        for (int t = 0; t < NTW; t++)
#pragma unroll
            for (int q = 0; q < 4; q++) acc[f][t][q] = 0.f;

    // per-lane ldmatrix address components
    uint32_t lrow = lane & 7, quad = lane >> 3;
    uint32_t aoff = sb +
                    (wm * 32 + lrow + ((quad & 1) << 3)) * PITCH + ((quad & 2) << 3);
    uint32_t boff = sb + (uint32_t)(2 * ASZ) +
                    (wn * (COUT / 2) + lrow + ((quad & 2) << 2)) * PITCH + ((quad & 1) << 4);

    for (int c = 0; c < 2; c++) {
        // ---- stage A chunk [128 x 64] fp32 -> bf16 hi/lo -------------------
        {
            int r = tid >> 1, half = tid & 1;
            int gr = row0 + r;
            const float* ip = in + (size_t)gr * CIN + c * 64 + half * 32;
            __nv_bfloat162* arh = reinterpret_cast<__nv_bfloat162*>(Ah + r * PITCH + half * 64);
            __nv_bfloat162* arl = reinterpret_cast<__nv_bfloat162*>(Al + r * PITCH + half * 64);
#pragma unroll
            for (int q = 0; q < 8; q++) {
                float4 v = make_float4(0.f, 0.f, 0.f, 0.f);
                if (gr < NN) v = *reinterpret_cast<const float4*>(ip + q * 4);
                if (RELU_IN) {
                    float4 b = *reinterpret_cast<const float4*>(bin + c * 64 + half * 32 + q * 4);
                    v.x = fmaxf(v.x + b.x, 0.f); v.y = fmaxf(v.y + b.y, 0.f);
                    v.z = fmaxf(v.z + b.z, 0.f); v.w = fmaxf(v.w + b.w, 0.f);
                }
                __nv_bfloat162 h0, h1, l0, l1;
                h0.x = __float2bfloat16_rn(v.x); h0.y = __float2bfloat16_rn(v.y);
                h1.x = __float2bfloat16_rn(v.z); h1.y = __float2bfloat16_rn(v.w);
                l0.x = __float2bfloat16_rn(v.x - __bfloat162float(h0.x));
                l0.y = __float2bfloat16_rn(v.y - __bfloat162float(h0.y));
                l1.x = __float2bfloat16_rn(v.z - __bfloat162float(h1.x));
                l1.y = __float2bfloat16_rn(v.w - __bfloat162float(h1.y));
                arh[q * 2] = h0; arh[q * 2 + 1] = h1;
                arl[q * 2] = l0; arl[q * 2 + 1] = l1;
            }
        }
        // ---- stage B chunk [COUT x 64] bf16 copy ---------------------------
        {
            constexpr int TPR = 256 / COUT;    // 2 or 4
            constexpr int VPT = 8 / TPR;       // uint4 per thread: 4 or 2
            int n = tid / TPR, part = tid % TPR;
            const uint4* sh = reinterpret_cast<const uint4*>(wh + n * 128 + c * 64) + part * VPT;
            const uint4* sl = reinterpret_cast<const uint4*>(wl + n * 128 + c * 64) + part * VPT;
            uint4* dh = reinterpret_cast<uint4*>(Bh + n * PITCH) + part * VPT;
            uint4* dl = reinterpret_cast<uint4*>(Bl + n * PITCH) + part * VPT;
#pragma unroll
            for (int v = 0; v < VPT; v++) { dh[v] = sh[v]; dl[v] = sl[v]; }
        }
        __syncthreads();

        // ---- compute: 4 k16 steps ------------------------------------------
#pragma unroll
        for (int kk = 0; kk < 4; kk++) {
            uint32_t ka = (uint32_t)(kk << 5);
            uint32_t afr[2][4], afl[2][4];
            ldsm4(afr[0], aoff + ka);
            ldsm4(afr[1], aoff + 16 * PITCH + ka);
            ldsm4(afl[0], aoff + ASZ + ka);
            ldsm4(afl[1], aoff + ASZ + 16 * PITCH + ka);
#pragma unroll
            for (int tp = 0; tp < NTW / 2; tp++) {
                uint32_t bfr[4], bfl[4];
                ldsm4(bfr, boff + tp * 16 * PITCH + ka);
                ldsm4(bfl, boff + BSZ + tp * 16 * PITCH + ka);
#pragma unroll
                for (int f = 0; f < 2; f++) {
                    mma16816(acc[f][2 * tp],     afr[f], bfr[0], bfr[1]);
                    mma16816(acc[f][2 * tp],     afl[f], bfr[0], bfr[1]);
                    mma16816(acc[f][2 * tp],     afr[f], bfl[0], bfl[1]);
                    mma16816(acc[f][2 * tp + 1], afr[f], bfr[2], bfr[3]);
                    mma16816(acc[f][2 * tp + 1], afl[f], bfr[2], bfr[3]);
                    mma16816(acc[f][2 * tp + 1], afr[f], bfl[2], bfl[3]);
                }
            }
        }
        __syncthreads();
    }

    // ---- epilogue: scale by dis, store h' as fp16 ---------------------------
#pragma unroll
    for (int f = 0; f < 2; f++) {
        int r0g = row0 + wm * 32 + f * 16 + (lane >> 2);
        float ds0 = (r0g < NN) ? g_dis[r0g] : 0.f;
        float ds1 = (r0g + 8 < NN) ? g_dis[r0g + 8] : 0.f;
#pragma unroll
        for (int t = 0; t < NTW; t++) {
            int ncol = wn * (COUT / 2) + t * 8 + ((lane & 3) << 1);
            if (r0g < NN) {
                __half2 o = __floats2half2_rn(acc[f][t][0] * ds0, acc[f][t][1] * ds0);
                *reinterpret_cast<__half2*>(h + (size_t)r0g * COUT + ncol) = o;
            }
            if (r0g + 8 < NN) {
                __half2 o = __floats2half2_rn(acc[f][t][2] * ds1, acc[f][t][3] * ds1);
                *reinterpret_cast<__half2*>(h + (size_t)(r0g + 8) * COUT + ncol) = o;
            }
        }
    }
}

// ---------------- gather: agg[d] = dis[d]*(sum_src h'[src] + h'[d]) ----------
// h' rows are 128 fp16 = 32 uint2; lane handles 4 channels (8 B).
__global__ void k_gather128(const __half* __restrict__ h, float* __restrict__ agg)
{
    int warp = (blockIdx.x * blockDim.x + threadIdx.x) >> 5;
    int lane = threadIdx.x & 31;
    if (warp >= NN) return;
    int beg = g_off[warp], end = g_off[warp + 1];
    const uint2* hp = reinterpret_cast<const uint2*>(h);
    float4 acc = h4_to_f4(hp[warp * 32 + lane]);       // self term
    int i = beg;
    for (; i + 4 <= end; i += 4) {
        float4 v0 = h4_to_f4(hp[g_ep[i    ] * 32 + lane]);
        float4 v1 = h4_to_f4(hp[g_ep[i + 1] * 32 + lane]);
        float4 v2 = h4_to_f4(hp[g_ep[i + 2] * 32 + lane]);
        float4 v3 = h4_to_f4(hp[g_ep[i + 3] * 32 + lane]);
        acc.x += (v0.x + v1.x) + (v2.x + v3.x);
        acc.y += (v0.y + v1.y) + (v2.y + v3.y);
        acc.z += (v0.z + v1.z) + (v2.z + v3.z);
        acc.w += (v0.w + v1.w) + (v2.w + v3.w);
    }
    for (; i < end; i++) {
        float4 v = h4_to_f4(hp[g_ep[i] * 32 + lane]);
        acc.x += v.x; acc.y += v.y; acc.z += v.z; acc.w += v.w;
    }
    float dd = g_dis[warp];
    acc.x *= dd; acc.y *= dd; acc.z *= dd; acc.w *= dd;
    float4* ap = reinterpret_cast<float4*>(agg);
    ap[warp * 32 + lane] = acc;
}

// final layer: COUT=64 (rows are 64 fp16 = 32 uints; lane handles 2 ch),
// fused +b3, writes fp32 straight to out
__global__ void k_gather64f(const __half* __restrict__ h, const float* __restrict__ b3,
                            float* __restrict__ out)
{
    int warp = (blockIdx.x * blockDim.x + threadIdx.x) >> 5;
    int lane = threadIdx.x & 31;
    if (warp >= NN) return;
    int beg = g_off[warp], end = g_off[warp + 1];
    const uint32_t* hp = reinterpret_cast<const uint32_t*>(h);
    uint32_t su = hp[warp * 32 + lane];
    float2 acc = __half22float2(*reinterpret_cast<__half2*>(&su));  // self term
    int i = beg;
    for (; i + 4 <= end; i += 4) {
        uint32_t u0 = hp[g_ep[i    ] * 32 + lane];
        uint32_t u1 = hp[g_ep[i + 1] * 32 + lane];
        uint32_t u2 = hp[g_ep[i + 2] * 32 + lane];
        uint32_t u3 = hp[g_ep[i + 3] * 32 + lane];
        float2 v0 = __half22float2(*reinterpret_cast<__half2*>(&u0));
        float2 v1 = __half22float2(*reinterpret_cast<__half2*>(&u1));
        float2 v2 = __half22float2(*reinterpret_cast<__half2*>(&u2));
        float2 v3 = __half22float2(*reinterpret_cast<__half2*>(&u3));
        acc.x += (v0.x + v1.x) + (v2.x + v3.x);
        acc.y += (v0.y + v1.y) + (v2.y + v3.y);
    }
    for (; i < end; i++) {
        uint32_t u = hp[g_ep[i] * 32 + lane];
        float2 v = __half22float2(*reinterpret_cast<__half2*>(&u));
        acc.x += v.x; acc.y += v.y;
    }
    float dd = g_dis[warp];
    float2 b = reinterpret_cast<const float2*>(b3)[lane];
    float2 r;
    r.x = fmaf(acc.x, dd, b.x);
    r.y = fmaf(acc.y, dd, b.y);
    reinterpret_cast<float2*>(out)[warp * 32 + lane] = r;
}

// ---------------- launcher ---------------------------------------------------
extern "C" void kernel_launch(void* const* d_in, const int* in_sizes, int n_in,
                              void* d_out, int out_size)
{
    const float* x  = (const float*)d_in[0];
    const int*   ei = (const int*)d_in[1];
    const float* W1 = (const float*)d_in[2];
    const float* b1 = (const float*)d_in[3];
    const float* W2 = (const float*)d_in[4];
    const float* b2 = (const float*)d_in[5];
    const float* W3 = (const float*)d_in[6];
    const float* b3 = (const float*)d_in[7];
    float* out = (float*)d_out;

    const int* src = ei;            // edge_index[0]
    const int* dst = ei + NE;       // edge_index[1]

    __half* ph = nullptr; float* pa = nullptr;
    cudaGetSymbolAddress((void**)&ph, g_h);
    cudaGetSymbolAddress((void**)&pa, g_a);
    __nv_bfloat16 *w1h, *w1l, *w2h, *w2l, *w3h, *w3l;
    cudaGetSymbolAddress((void**)&w1h, g_w1h);
    cudaGetSymbolAddress((void**)&w1l, g_w1l);
    cudaGetSymbolAddress((void**)&w2h, g_w2h);
    cudaGetSymbolAddress((void**)&w2l, g_w2l);
    cudaGetSymbolAddress((void**)&w3h, g_w3h);
    cudaGetSymbolAddress((void**)&w3l, g_w3l);

    const int smem128 = 2 * 128 * 144 + 2 * 128 * 144;   // 73728
    const int smem64  = 2 * 128 * 144 + 2 * 64 * 144;    // 55296
    cudaFuncSetAttribute(k_gemm_mma<128, false>, cudaFuncAttributeMaxDynamicSharedMemorySize, smem128);
    cudaFuncSetAttribute(k_gemm_mma<128, true>,  cudaFuncAttributeMaxDynamicSharedMemorySize, smem128);
    cudaFuncSetAttribute(k_gemm_mma<64,  true>,  cudaFuncAttributeMaxDynamicSharedMemorySize, smem64);

    const int gB = (NN + 127) / 128;         // 782 M-tiles
    const int gG = (NN * 32 + 255) / 256;    // warp per node

    // setup
    k_init<<<NBLK, 256>>>(W1, W2, W3);
    k_deg_count<<<(NE + 255) / 256, 256>>>(dst);
    k_scan1<<<NBLK, 256>>>();
    k_scan2<<<1, 512>>>();
    k_scan3<<<NBLK, 256>>>();

    // layer 1 (gemm first; CSR fill overlaps before gather needs it)
    k_gemm_mma<128, false><<<gB, 256, smem128>>>(x, w1h, w1l, b1, ph);
    k_fill<<<(NE + 255) / 256, 256>>>(src, dst);
    k_gather128<<<gG, 256>>>(ph, pa);
    // layer 2
    k_gemm_mma<128, true><<<gB, 256, smem128>>>(pa, w2h, w2l, b1, ph);
    k_gather128<<<gG, 256>>>(ph, pa);
    // layer 3 (COUT=64) + fused final bias
    k_gemm_mma<64, true><<<gB, 256, smem64>>>(pa, w3h, w3l, b2, ph);
    k_gather64f<<<gG, 256>>>(ph, b3, out);
}

// round 8
// speedup vs baseline: 1.2529x; 1.1066x over previous
#include <cuda_runtime.h>
#include <cuda_bf16.h>
#include <cuda_fp16.h>
#include <cstdint>

#define NN 100000
#define NE 1600000
#define CIN 128
#define NBLK ((NN + 255) / 256)   // 391 scan blocks

// ---------------- scratch ---------------------------------------------------
static __device__ int    g_deg[NN];
static __device__ int    g_cur[NN];
static __device__ float  g_dis[NN];
static __device__ int    g_off[NN + 1];
static __device__ int    g_bsum[512];
static __device__ int    g_bscan[512];
static __device__ int    g_ep[NE];                 // src per (dst-sorted) edge
static __device__ __half g_h[(size_t)NN * 128];    // dis-scaled messages (fp16)
static __device__ __half g_a[(size_t)NN * 128];    // relu(agg+b) layer input (fp16)
// pre-transposed + bf16 hi/lo split weights: [COUT][CIN] bf16
static __device__ __nv_bfloat16 g_w1h[128 * 128], g_w1l[128 * 128];
static __device__ __nv_bfloat16 g_w2h[128 * 128], g_w2l[128 * 128];
static __device__ __nv_bfloat16 g_w3h[64 * 128],  g_w3l[64 * 128];

// ---------------- PTX helpers ------------------------------------------------
__device__ __forceinline__ uint32_t smem_u32(const void* p) {
    uint32_t a;
    asm("{ .reg .u64 t; cvta.to.shared.u64 t, %1; cvt.u32.u64 %0, t; }" : "=r"(a) : "l"(p));
    return a;
}
__device__ __forceinline__ void ldsm4(uint32_t* r, uint32_t addr) {
    asm volatile("ldmatrix.sync.aligned.m8n8.x4.shared.b16 {%0,%1,%2,%3}, [%4];"
                 : "=r"(r[0]), "=r"(r[1]), "=r"(r[2]), "=r"(r[3]) : "r"(addr));
}
__device__ __forceinline__ void mma16816(float* d, const uint32_t* a,
                                         uint32_t b0, uint32_t b1) {
    asm volatile(
        "mma.sync.aligned.m16n8k16.row.col.f32.bf16.bf16.f32 "
        "{%0,%1,%2,%3}, {%4,%5,%6,%7}, {%8,%9}, {%0,%1,%2,%3};"
        : "+f"(d[0]), "+f"(d[1]), "+f"(d[2]), "+f"(d[3])
        : "r"(a[0]), "r"(a[1]), "r"(a[2]), "r"(a[3]), "r"(b0), "r"(b1));
}
__device__ __forceinline__ float4 h4_to_f4(uint2 u) {
    float2 a = __half22float2(*reinterpret_cast<__half2*>(&u.x));
    float2 b = __half22float2(*reinterpret_cast<__half2*>(&u.y));
    return make_float4(a.x, a.y, b.x, b.y);
}

// ---------------- init: self-loop degree + weight transpose/split ------------
__global__ void k_init(const float* __restrict__ W1, const float* __restrict__ W2,
                       const float* __restrict__ W3) {
    int i = blockIdx.x * blockDim.x + threadIdx.x;
    if (i < NN) g_deg[i] = 1;                       // self loop
    if (i < 16384) {
        int k = i >> 7, n = i & 127;
        float v = W1[i];
        __nv_bfloat16 hi = __float2bfloat16_rn(v);
        g_w1h[n * 128 + k] = hi;
        g_w1l[n * 128 + k] = __float2bfloat16_rn(v - __bfloat162float(hi));
        v = W2[i]; hi = __float2bfloat16_rn(v);
        g_w2h[n * 128 + k] = hi;
        g_w2l[n * 128 + k] = __float2bfloat16_rn(v - __bfloat162float(hi));
    }
    if (i < 8192) {
        int k = i >> 6, n = i & 63;
        float v = W3[i];
        __nv_bfloat16 hi = __float2bfloat16_rn(v);
        g_w3h[n * 128 + k] = hi;
        g_w3l[n * 128 + k] = __float2bfloat16_rn(v - __bfloat162float(hi));
    }
}
__global__ void k_deg_count(const int* __restrict__ dst) {
    int e = blockIdx.x * blockDim.x + threadIdx.x;
    if (e < NE) atomicAdd(&g_deg[dst[e]], 1);
}

// ---------------- CSR build (dis fused into scan1) ---------------------------
__global__ void k_scan1() {
    __shared__ int s[256];
    int t = threadIdx.x;
    int i = blockIdx.x * 256 + t;
    int deg = (i < NN) ? g_deg[i] : 1;
    if (i < NN) g_dis[i] = rsqrtf((float)deg);
    int v = (i < NN) ? (deg - 1) : 0;
    s[t] = v; __syncthreads();
#pragma unroll
    for (int off = 1; off < 256; off <<= 1) {
        int a = (t >= off) ? s[t - off] : 0;
        __syncthreads();
        s[t] += a; __syncthreads();
    }
    if (i < NN) g_off[i] = s[t] - v;
    if (t == 255) g_bsum[blockIdx.x] = s[255];
}
__global__ void k_scan2() {
    __shared__ int s[512];
    int t = threadIdx.x;
    int v = (t < NBLK) ? g_bsum[t] : 0;
    s[t] = v; __syncthreads();
#pragma unroll
    for (int off = 1; off < 512; off <<= 1) {
        int a = (t >= off) ? s[t - off] : 0;
        __syncthreads();
        s[t] += a; __syncthreads();
    }
    g_bscan[t] = s[t] - v;
}
__global__ void k_scan3() {
    int i = blockIdx.x * blockDim.x + threadIdx.x;
    if (i < NN) {
        int o = g_off[i] + g_bscan[i >> 8];
        g_off[i] = o;
        g_cur[i] = o;
    }
    if (i == 0) g_off[NN] = NE;
}
__global__ void k_fill(const int* __restrict__ src, const int* __restrict__ dst) {
    int e = blockIdx.x * blockDim.x + threadIdx.x;
    if (e >= NE) return;
    int pos = atomicAdd(&g_cur[dst[e]], 1);
    g_ep[pos] = src[e];
}

// ---------------- bf16-split tensor-core GEMM: h' = fp16(dis * (in @ W)) -----
// in is fp32 (layer 1) or fp16 (layers 2,3; bias+relu already applied by the
// producing gather). D = Ah*Bh + Al*Bh + Ah*Bl (fp32 accum); fp16->bf16 hi/lo
// split is exact. 128-row tiles, K chunked by 64. 8 warps = 4(M) x 2(N).
template <int COUT, bool HALF_IN>
__global__ void __launch_bounds__(256)
k_gemm_mma(const void* __restrict__ in_, const __nv_bfloat16* __restrict__ wh,
           const __nv_bfloat16* __restrict__ wl, __half* __restrict__ h)
{
    constexpr int PITCH = 144;                 // bytes per smem row (72 bf16)
    constexpr int ASZ = 128 * PITCH;           // 18432
    constexpr int BSZ = COUT * PITCH;
    constexpr int NTW = COUT / 16;             // n8 tiles per warp (8 or 4)

    extern __shared__ char smem[];
    char* Ah = smem;
    char* Al = smem + ASZ;
    char* Bh = smem + 2 * ASZ;
    char* Bl = Bh + BSZ;
    uint32_t sb = smem_u32(smem);

    int tid = threadIdx.x;
    int wid = tid >> 5, lane = tid & 31;
    int wm = wid >> 1, wn = wid & 1;
    int row0 = blockIdx.x * 128;

    float acc[2][NTW][4];
#pragma unroll
    for (int f = 0; f < 2; f++)
#pragma unroll
        for (int t = 0; t < NTW; t++)
#pragma unroll
            for (int q = 0; q < 4; q++) acc[f][t][q] = 0.f;

    uint32_t lrow = lane & 7, quad = lane >> 3;
    uint32_t aoff = sb +
                    (wm * 32 + lrow + ((quad & 1) << 3)) * PITCH + ((quad & 2) << 3);
    uint32_t boff = sb + (uint32_t)(2 * ASZ) +
                    (wn * (COUT / 2) + lrow + ((quad & 2) << 2)) * PITCH + ((quad & 1) << 4);

    for (int c = 0; c < 2; c++) {
        // ---- stage A chunk [128 x 64] -> bf16 hi/lo ------------------------
        {
            int r = tid >> 1, half = tid & 1;
            int gr = row0 + r;
            __nv_bfloat162* arh = reinterpret_cast<__nv_bfloat162*>(Ah + r * PITCH + half * 64);
            __nv_bfloat162* arl = reinterpret_cast<__nv_bfloat162*>(Al + r * PITCH + half * 64);
#pragma unroll
            for (int q = 0; q < 8; q++) {
                float4 v = make_float4(0.f, 0.f, 0.f, 0.f);
                if (gr < NN) {
                    if (HALF_IN) {
                        const __half* ip = (const __half*)in_ +
                            (size_t)gr * CIN + c * 64 + half * 32 + q * 4;
                        v = h4_to_f4(*reinterpret_cast<const uint2*>(ip));
                    } else {
                        const float* ip = (const float*)in_ +
                            (size_t)gr * CIN + c * 64 + half * 32 + q * 4;
                        v = *reinterpret_cast<const float4*>(ip);
                    }
                }
                __nv_bfloat162 h0, h1, l0, l1;
                h0.x = __float2bfloat16_rn(v.x); h0.y = __float2bfloat16_rn(v.y);
                h1.x = __float2bfloat16_rn(v.z); h1.y = __float2bfloat16_rn(v.w);
                l0.x = __float2bfloat16_rn(v.x - __bfloat162float(h0.x));
                l0.y = __float2bfloat16_rn(v.y - __bfloat162float(h0.y));
                l1.x = __float2bfloat16_rn(v.z - __bfloat162float(h1.x));
                l1.y = __float2bfloat16_rn(v.w - __bfloat162float(h1.y));
                arh[q * 2] = h0; arh[q * 2 + 1] = h1;
                arl[q * 2] = l0; arl[q * 2 + 1] = l1;
            }
        }
        // ---- stage B chunk [COUT x 64] bf16 copy ---------------------------
        {
            constexpr int TPR = 256 / COUT;    // 2 or 4
            constexpr int VPT = 8 / TPR;       // uint4 per thread: 4 or 2
            int n = tid / TPR, part = tid % TPR;
            const uint4* sh = reinterpret_cast<const uint4*>(wh + n * 128 + c * 64) + part * VPT;
            const uint4* sl = reinterpret_cast<const uint4*>(wl + n * 128 + c * 64) + part * VPT;
            uint4* dh = reinterpret_cast<uint4*>(Bh + n * PITCH) + part * VPT;
            uint4* dl = reinterpret_cast<uint4*>(Bl + n * PITCH) + part * VPT;
#pragma unroll
            for (int v = 0; v < VPT; v++) { dh[v] = sh[v]; dl[v] = sl[v]; }
        }
        __syncthreads();

        // ---- compute: 4 k16 steps ------------------------------------------
#pragma unroll
        for (int kk = 0; kk < 4; kk++) {
            uint32_t ka = (uint32_t)(kk << 5);
            uint32_t afr[2][4], afl[2][4];
            ldsm4(afr[0], aoff + ka);
            ldsm4(afr[1], aoff + 16 * PITCH + ka);
            ldsm4(afl[0], aoff + ASZ + ka);
            ldsm4(afl[1], aoff + ASZ + 16 * PITCH + ka);
#pragma unroll
            for (int tp = 0; tp < NTW / 2; tp++) {
                uint32_t bfr[4], bfl[4];
                ldsm4(bfr, boff + tp * 16 * PITCH + ka);
                ldsm4(bfl, boff + BSZ + tp * 16 * PITCH + ka);
#pragma unroll
                for (int f = 0; f < 2; f++) {
                    mma16816(acc[f][2 * tp],     afr[f], bfr[0], bfr[1]);
                    mma16816(acc[f][2 * tp],     afl[f], bfr[0], bfr[1]);
                    mma16816(acc[f][2 * tp],     afr[f], bfl[0], bfl[1]);
                    mma16816(acc[f][2 * tp + 1], afr[f], bfr[2], bfr[3]);
                    mma16816(acc[f][2 * tp + 1], afl[f], bfr[2], bfr[3]);
                    mma16816(acc[f][2 * tp + 1], afr[f], bfl[2], bfl[3]);
                }
            }
        }
        __syncthreads();
    }

    // ---- epilogue: scale by dis, store h' as fp16 ---------------------------
#pragma unroll
    for (int f = 0; f < 2; f++) {
        int r0g = row0 + wm * 32 + f * 16 + (lane >> 2);
        float ds0 = (r0g < NN) ? g_dis[r0g] : 0.f;
        float ds1 = (r0g + 8 < NN) ? g_dis[r0g + 8] : 0.f;
#pragma unroll
        for (int t = 0; t < NTW; t++) {
            int ncol = wn * (COUT / 2) + t * 8 + ((lane & 3) << 1);
            if (r0g < NN) {
                __half2 o = __floats2half2_rn(acc[f][t][0] * ds0, acc[f][t][1] * ds0);
                *reinterpret_cast<__half2*>(h + (size_t)r0g * COUT + ncol) = o;
            }
            if (r0g + 8 < NN) {
                __half2 o = __floats2half2_rn(acc[f][t][2] * ds1, acc[f][t][3] * ds1);
                *reinterpret_cast<__half2*>(h + (size_t)(r0g + 8) * COUT + ncol) = o;
            }
        }
    }
}

// ---------------- gather (layers 1,2): next_in = fp16(relu(dis*sum + b)) -----
// h' rows are 128 fp16 = 32 uint2; lane handles 4 channels (8 B).
__global__ void k_gather128(const __half* __restrict__ h, const float* __restrict__ bias,
                            __half* __restrict__ nxt)
{
    int warp = (blockIdx.x * blockDim.x + threadIdx.x) >> 5;
    int lane = threadIdx.x & 31;
    if (warp >= NN) return;
    int beg = g_off[warp], end = g_off[warp + 1];
    const uint2* hp = reinterpret_cast<const uint2*>(h);
    float4 acc = h4_to_f4(hp[warp * 32 + lane]);       // self term
    int i = beg;
    for (; i + 4 <= end; i += 4) {
        float4 v0 = h4_to_f4(hp[g_ep[i    ] * 32 + lane]);
        float4 v1 = h4_to_f4(hp[g_ep[i + 1] * 32 + lane]);
        float4 v2 = h4_to_f4(hp[g_ep[i + 2] * 32 + lane]);
        float4 v3 = h4_to_f4(hp[g_ep[i + 3] * 32 + lane]);
        acc.x += (v0.x + v1.x) + (v2.x + v3.x);
        acc.y += (v0.y + v1.y) + (v2.y + v3.y);
        acc.z += (v0.z + v1.z) + (v2.z + v3.z);
        acc.w += (v0.w + v1.w) + (v2.w + v3.w);
    }
    for (; i < end; i++) {
        float4 v = h4_to_f4(hp[g_ep[i] * 32 + lane]);
        acc.x += v.x; acc.y += v.y; acc.z += v.z; acc.w += v.w;
    }
    float dd = g_dis[warp];
    float4 b = reinterpret_cast<const float4*>(bias)[lane];
    float rx = fmaxf(fmaf(acc.x, dd, b.x), 0.f);
    float ry = fmaxf(fmaf(acc.y, dd, b.y), 0.f);
    float rz = fmaxf(fmaf(acc.z, dd, b.z), 0.f);
    float rw = fmaxf(fmaf(acc.w, dd, b.w), 0.f);
    uint2 o;
    __half2 o0 = __floats2half2_rn(rx, ry);
    __half2 o1 = __floats2half2_rn(rz, rw);
    o.x = *reinterpret_cast<uint32_t*>(&o0);
    o.y = *reinterpret_cast<uint32_t*>(&o1);
    reinterpret_cast<uint2*>(nxt)[warp * 32 + lane] = o;
}

// final layer: COUT=64 (rows 64 fp16 = 32 uints; lane handles 2 ch),
// fused +b3, fp32 straight to out
__global__ void k_gather64f(const __half* __restrict__ h, const float* __restrict__ b3,
                            float* __restrict__ out)
{
    int warp = (blockIdx.x * blockDim.x + threadIdx.x) >> 5;
    int lane = threadIdx.x & 31;
    if (warp >= NN) return;
    int beg = g_off[warp], end = g_off[warp + 1];
    const uint32_t* hp = reinterpret_cast<const uint32_t*>(h);
    uint32_t su = hp[warp * 32 + lane];
    float2 acc = __half22float2(*reinterpret_cast<__half2*>(&su));  // self term
    int i = beg;
    for (; i + 4 <= end; i += 4) {
        uint32_t u0 = hp[g_ep[i    ] * 32 + lane];
        uint32_t u1 = hp[g_ep[i + 1] * 32 + lane];
        uint32_t u2 = hp[g_ep[i + 2] * 32 + lane];
        uint32_t u3 = hp[g_ep[i + 3] * 32 + lane];
        float2 v0 = __half22float2(*reinterpret_cast<__half2*>(&u0));
        float2 v1 = __half22float2(*reinterpret_cast<__half2*>(&u1));
        float2 v2 = __half22float2(*reinterpret_cast<__half2*>(&u2));
        float2 v3 = __half22float2(*reinterpret_cast<__half2*>(&u3));
        acc.x += (v0.x + v1.x) + (v2.x + v3.x);
        acc.y += (v0.y + v1.y) + (v2.y + v3.y);
    }
    for (; i < end; i++) {
        uint32_t u = hp[g_ep[i] * 32 + lane];
        float2 v = __half22float2(*reinterpret_cast<__half2*>(&u));
        acc.x += v.x; acc.y += v.y;
    }
    float dd = g_dis[warp];
    float2 b = reinterpret_cast<const float2*>(b3)[lane];
    float2 r;
    r.x = fmaf(acc.x, dd, b.x);
    r.y = fmaf(acc.y, dd, b.y);
    reinterpret_cast<float2*>(out)[warp * 32 + lane] = r;
}

// ---------------- launcher ---------------------------------------------------
extern "C" void kernel_launch(void* const* d_in, const int* in_sizes, int n_in,
                              void* d_out, int out_size)
{
    const float* x  = (const float*)d_in[0];
    const int*   ei = (const int*)d_in[1];
    const float* W1 = (const float*)d_in[2];
    const float* b1 = (const float*)d_in[3];
    const float* W2 = (const float*)d_in[4];
    const float* b2 = (const float*)d_in[5];
    const float* W3 = (const float*)d_in[6];
    const float* b3 = (const float*)d_in[7];
    float* out = (float*)d_out;

    const int* src = ei;            // edge_index[0]
    const int* dst = ei + NE;       // edge_index[1]

    __half *ph = nullptr, *pa = nullptr;
    cudaGetSymbolAddress((void**)&ph, g_h);
    cudaGetSymbolAddress((void**)&pa, g_a);
    __nv_bfloat16 *w1h, *w1l, *w2h, *w2l, *w3h, *w3l;
    cudaGetSymbolAddress((void**)&w1h, g_w1h);
    cudaGetSymbolAddress((void**)&w1l, g_w1l);
    cudaGetSymbolAddress((void**)&w2h, g_w2h);
    cudaGetSymbolAddress((void**)&w2l, g_w2l);
    cudaGetSymbolAddress((void**)&w3h, g_w3h);
    cudaGetSymbolAddress((void**)&w3l, g_w3l);

    const int smem128 = 2 * 128 * 144 + 2 * 128 * 144;   // 73728
    const int smem64  = 2 * 128 * 144 + 2 * 64 * 144;    // 55296
    cudaFuncSetAttribute(k_gemm_mma<128, false>, cudaFuncAttributeMaxDynamicSharedMemorySize, smem128);
    cudaFuncSetAttribute(k_gemm_mma<128, true>,  cudaFuncAttributeMaxDynamicSharedMemorySize, smem128);
    cudaFuncSetAttribute(k_gemm_mma<64,  true>,  cudaFuncAttributeMaxDynamicSharedMemorySize, smem64);

    const int gB = (NN + 127) / 128;         // 782 M-tiles
    const int gG = (NN * 32 + 255) / 256;    // warp per node

    // launch order arranged so gemm1 is the 4th launch (ncu profiles #4)
    k_init<<<NBLK, 256>>>(W1, W2, W3);                                   // 1
    k_deg_count<<<(NE + 255) / 256, 256>>>(dst);                         // 2
    k_scan1<<<NBLK, 256>>>();                                            // 3
    k_gemm_mma<128, false><<<gB, 256, smem128>>>(x, w1h, w1l, ph);       // 4 <- profiled
    k_scan2<<<1, 512>>>();                                               // 5
    k_scan3<<<NBLK, 256>>>();                                            // 6
    k_fill<<<(NE + 255) / 256, 256>>>(src, dst);                         // 7
    // gather1 applies b1 + relu, emits fp16 input for layer 2
    k_gather128<<<gG, 256>>>(ph, b1, pa);                                // 8
    k_gemm_mma<128, true><<<gB, 256, smem128>>>(pa, w2h, w2l, ph);       // 9
    k_gather128<<<gG, 256>>>(ph, b2, pa);                                // 10
    k_gemm_mma<64, true><<<gB, 256, smem64>>>(pa, w3h, w3l, ph);         // 11
    k_gather64f<<<gG, 256>>>(ph, b3, out);                               // 12
}

// round 10
// speedup vs baseline: 1.2816x; 1.0229x over previous
#include <cuda_runtime.h>
#include <cuda_fp16.h>
#include <cstdint>

#define NN 100000
#define NE 1600000
#define CIN 128
#define NBLK ((NN + 255) / 256)   // 391 scan blocks

// ---------------- scratch ---------------------------------------------------
static __device__ int    g_deg[NN];
static __device__ int    g_cur[NN];
static __device__ float  g_dis[NN];
static __device__ int    g_off[NN + 1];
static __device__ int    g_bsum[512];
static __device__ int    g_bscan[512];
static __device__ int    g_ep[NE];                 // src per (dst-sorted) edge
static __device__ __half g_h[(size_t)NN * 128];    // dis-scaled messages (fp16)
static __device__ __half g_a[(size_t)NN * 128];    // relu(agg+b) layer input (fp16)
// pre-transposed + fp16 hi/lo split weights: [COUT][CIN]
static __device__ __half g_w1h[128 * 128], g_w1l[128 * 128];
static __device__ __half g_w2h[128 * 128], g_w2l[128 * 128];
static __device__ __half g_w3h[64 * 128],  g_w3l[64 * 128];

// ---------------- PTX helpers ------------------------------------------------
__device__ __forceinline__ uint32_t smem_u32(const void* p) {
    uint32_t a;
    asm("{ .reg .u64 t; cvta.to.shared.u64 t, %1; cvt.u32.u64 %0, t; }" : "=r"(a) : "l"(p));
    return a;
}
__device__ __forceinline__ void ldsm4(uint32_t* r, uint32_t addr) {
    asm volatile("ldmatrix.sync.aligned.m8n8.x4.shared.b16 {%0,%1,%2,%3}, [%4];"
                 : "=r"(r[0]), "=r"(r[1]), "=r"(r[2]), "=r"(r[3]) : "r"(addr));
}
__device__ __forceinline__ void mma16816(float* d, const uint32_t* a,
                                         uint32_t b0, uint32_t b1) {
    asm volatile(
        "mma.sync.aligned.m16n8k16.row.col.f32.f16.f16.f32 "
        "{%0,%1,%2,%3}, {%4,%5,%6,%7}, {%8,%9}, {%0,%1,%2,%3};"
        : "+f"(d[0]), "+f"(d[1]), "+f"(d[2]), "+f"(d[3])
        : "r"(a[0]), "r"(a[1]), "r"(a[2]), "r"(a[3]), "r"(b0), "r"(b1));
}
__device__ __forceinline__ float4 h4_to_f4(uint2 u) {
    float2 a = __half22float2(*reinterpret_cast<__half2*>(&u.x));
    float2 b = __half22float2(*reinterpret_cast<__half2*>(&u.y));
    return make_float4(a.x, a.y, b.x, b.y);
}

// ---------------- init: self-loop degree + weight transpose/split ------------
__global__ void k_init(const float* __restrict__ W1, const float* __restrict__ W2,
                       const float* __restrict__ W3) {
    int i = blockIdx.x * blockDim.x + threadIdx.x;
    if (i < NN) g_deg[i] = 1;                       // self loop
    if (i < 16384) {
        int k = i >> 7, n = i & 127;
        float v = W1[i];
        __half hi = __float2half_rn(v);
        g_w1h[n * 128 + k] = hi;
        g_w1l[n * 128 + k] = __float2half_rn(v - __half2float(hi));
        v = W2[i]; hi = __float2half_rn(v);
        g_w2h[n * 128 + k] = hi;
        g_w2l[n * 128 + k] = __float2half_rn(v - __half2float(hi));
    }
    if (i < 8192) {
        int k = i >> 6, n = i & 63;
        float v = W3[i];
        __half hi = __float2half_rn(v);
        g_w3h[n * 128 + k] = hi;
        g_w3l[n * 128 + k] = __float2half_rn(v - __half2float(hi));
    }
}
__global__ void k_deg_count(const int* __restrict__ dst) {
    int e = blockIdx.x * blockDim.x + threadIdx.x;
    if (e < NE) atomicAdd(&g_deg[dst[e]], 1);
}

// ---------------- CSR build (dis fused into scan1) ---------------------------
__global__ void k_scan1() {
    __shared__ int s[256];
    int t = threadIdx.x;
    int i = blockIdx.x * 256 + t;
    int deg = (i < NN) ? g_deg[i] : 1;
    if (i < NN) g_dis[i] = rsqrtf((float)deg);
    int v = (i < NN) ? (deg - 1) : 0;
    s[t] = v; __syncthreads();
#pragma unroll
    for (int off = 1; off < 256; off <<= 1) {
        int a = (t >= off) ? s[t - off] : 0;
        __syncthreads();
        s[t] += a; __syncthreads();
    }
    if (i < NN) g_off[i] = s[t] - v;
    if (t == 255) g_bsum[blockIdx.x] = s[255];
}
__global__ void k_scan2() {
    __shared__ int s[512];
    int t = threadIdx.x;
    int v = (t < NBLK) ? g_bsum[t] : 0;
    s[t] = v; __syncthreads();
#pragma unroll
    for (int off = 1; off < 512; off <<= 1) {
        int a = (t >= off) ? s[t - off] : 0;
        __syncthreads();
        s[t] += a; __syncthreads();
    }
    g_bscan[t] = s[t] - v;
}
__global__ void k_scan3() {
    int i = blockIdx.x * blockDim.x + threadIdx.x;
    if (i < NN) {
        int o = g_off[i] + g_bscan[i >> 8];
        g_off[i] = o;
        g_cur[i] = o;
    }
    if (i == 0) g_off[NN] = NE;
}
__global__ void k_fill(const int* __restrict__ src, const int* __restrict__ dst) {
    int e = blockIdx.x * blockDim.x + threadIdx.x;
    if (e >= NE) return;
    int pos = atomicAdd(&g_cur[dst[e]], 1);
    g_ep[pos] = src[e];
}

// ---------------- fp16 tensor-core GEMM: h' = fp16(dis * (in @ W)) -----------
// Weights split w = wh + wl (fp16 each, 22-bit effective).
// HALF_IN (layers 2,3): A is exact fp16 -> D = A*wh + A*wl (2 MMAs, 1 A buf).
// fp32 in (layer 1): A split hi/lo fp16 -> D = Ah*wh + Al*wh + Ah*wl.
// 128-row tiles, K chunked by 64, rows padded to 144 B. 8 warps = 4(M) x 2(N).
template <int COUT, bool HALF_IN>
__global__ void __launch_bounds__(256)
k_gemm_mma(const void* __restrict__ in_, const __half* __restrict__ wh,
           const __half* __restrict__ wl, __half* __restrict__ h)
{
    constexpr int PITCH = 144;                 // bytes per smem row (72 halves)
    constexpr int ASZ = 128 * PITCH;           // 18432
    constexpr int BSZ = COUT * PITCH;
    constexpr int NAB = HALF_IN ? 1 : 2;       // A buffers
    constexpr int NTW = COUT / 16;             // n8-tile pairs per warp

    extern __shared__ char smem[];
    char* A0 = smem;                           // A (or A_hi)
    char* A1 = smem + ASZ;                     // A_lo (split mode only)
    char* Bh = smem + NAB * ASZ;
    char* Bl = Bh + BSZ;
    uint32_t sb = smem_u32(smem);

    int tid = threadIdx.x;
    int wid = tid >> 5, lane = tid & 31;
    int wm = wid >> 1, wn = wid & 1;
    int row0 = blockIdx.x * 128;

    float acc[2][NTW][4];
#pragma unroll
    for (int f = 0; f < 2; f++)
#pragma unroll
        for (int t = 0; t < NTW; t++)
#pragma unroll
            for (int q = 0; q < 4; q++) acc[f][t][q] = 0.f;

    uint32_t lrow = lane & 7, quad = lane >> 3;
    uint32_t aoff = sb +
                    (wm * 32 + lrow + ((quad & 1) << 3)) * PITCH + ((quad & 2) << 3);
    uint32_t boff = sb + (uint32_t)(NAB * ASZ) +
                    (wn * (COUT / 2) + lrow + ((quad & 2) << 2)) * PITCH + ((quad & 1) << 4);

    for (int c = 0; c < 2; c++) {
        // ---- stage A chunk [128 x 64] --------------------------------------
        {
            int r = tid >> 1, half = tid & 1;
            int gr = row0 + r;
            if (HALF_IN) {
                // direct vectorized copy of fp16 rows (no conversion)
                const uint4* ip = reinterpret_cast<const uint4*>(
                    (const __half*)in_ + (size_t)gr * CIN + c * 64 + half * 32);
                uint4* ar = reinterpret_cast<uint4*>(A0 + r * PITCH + half * 64);
                if (gr < NN) {
#pragma unroll
                    for (int q = 0; q < 4; q++) ar[q] = ip[q];
                } else {
                    uint4 z = make_uint4(0, 0, 0, 0);
#pragma unroll
                    for (int q = 0; q < 4; q++) ar[q] = z;
                }
            } else {
                const float* ip = (const float*)in_ + (size_t)gr * CIN + c * 64 + half * 32;
                __half2* arh = reinterpret_cast<__half2*>(A0 + r * PITCH + half * 64);
                __half2* arl = reinterpret_cast<__half2*>(A1 + r * PITCH + half * 64);
#pragma unroll
                for (int q = 0; q < 8; q++) {
                    float4 v = make_float4(0.f, 0.f, 0.f, 0.f);
                    if (gr < NN) v = *reinterpret_cast<const float4*>(ip + q * 4);
                    __half2 h0 = __floats2half2_rn(v.x, v.y);
                    __half2 h1 = __floats2half2_rn(v.z, v.w);
                    __half2 l0 = __floats2half2_rn(v.x - __low2float(h0),
                                                   v.y - __high2float(h0));
                    __half2 l1 = __floats2half2_rn(v.z - __low2float(h1),
                                                   v.w - __high2float(h1));
                    arh[q * 2] = h0; arh[q * 2 + 1] = h1;
                    arl[q * 2] = l0; arl[q * 2 + 1] = l1;
                }
            }
        }
        // ---- stage B chunk [COUT x 64] fp16 copy ---------------------------
        {
            constexpr int TPR = 256 / COUT;    // 2 or 4
            constexpr int VPT = 8 / TPR;       // uint4 per thread: 4 or 2
            int n = tid / TPR, part = tid % TPR;
            const uint4* sh = reinterpret_cast<const uint4*>(wh + n * 128 + c * 64) + part * VPT;
            const uint4* sl = reinterpret_cast<const uint4*>(wl + n * 128 + c * 64) + part * VPT;
            uint4* dh = reinterpret_cast<uint4*>(Bh + n * PITCH) + part * VPT;
            uint4* dl = reinterpret_cast<uint4*>(Bl + n * PITCH) + part * VPT;
#pragma unroll
            for (int v = 0; v < VPT; v++) { dh[v] = sh[v]; dl[v] = sl[v]; }
        }
        __syncthreads();

        // ---- compute: 4 k16 steps ------------------------------------------
#pragma unroll
        for (int kk = 0; kk < 4; kk++) {
            uint32_t ka = (uint32_t)(kk << 5);
            uint32_t afr[2][4], afl[2][4];
            ldsm4(afr[0], aoff + ka);
            ldsm4(afr[1], aoff + 16 * PITCH + ka);
            if (!HALF_IN) {
                ldsm4(afl[0], aoff + ASZ + ka);
                ldsm4(afl[1], aoff + ASZ + 16 * PITCH + ka);
            }
#pragma unroll
            for (int tp = 0; tp < NTW / 2; tp++) {
                uint32_t bfr[4], bfl[4];
                ldsm4(bfr, boff + tp * 16 * PITCH + ka);
                ldsm4(bfl, boff + BSZ + tp * 16 * PITCH + ka);
#pragma unroll
                for (int f = 0; f < 2; f++) {
                    mma16816(acc[f][2 * tp],     afr[f], bfr[0], bfr[1]);
                    mma16816(acc[f][2 * tp],     afr[f], bfl[0], bfl[1]);
                    mma16816(acc[f][2 * tp + 1], afr[f], bfr[2], bfr[3]);
                    mma16816(acc[f][2 * tp + 1], afr[f], bfl[2], bfl[3]);
                    if (!HALF_IN) {
                        mma16816(acc[f][2 * tp],     afl[f], bfr[0], bfr[1]);
                        mma16816(acc[f][2 * tp + 1], afl[f], bfr[2], bfr[3]);
                    }
                }
            }
        }
        __syncthreads();
    }

    // ---- epilogue: scale by dis, store h' as fp16 ---------------------------
#pragma unroll
    for (int f = 0; f < 2; f++) {
        int r0g = row0 + wm * 32 + f * 16 + (lane >> 2);
        float ds0 = (r0g < NN) ? g_dis[r0g] : 0.f;
        float ds1 = (r0g + 8 < NN) ? g_dis[r0g + 8] : 0.f;
#pragma unroll
        for (int t = 0; t < NTW; t++) {
            int ncol = wn * (COUT / 2) + t * 8 + ((lane & 3) << 1);
            if (r0g < NN) {
                __half2 o = __floats2half2_rn(acc[f][t][0] * ds0, acc[f][t][1] * ds0);
                *reinterpret_cast<__half2*>(h + (size_t)r0g * COUT + ncol) = o;
            }
            if (r0g + 8 < NN) {
                __half2 o = __floats2half2_rn(acc[f][t][2] * ds1, acc[f][t][3] * ds1);
                *reinterpret_cast<__half2*>(h + (size_t)(r0g + 8) * COUT + ncol) = o;
            }
        }
    }
}

// ---------------- gather (layers 1,2): next_in = fp16(relu(dis*sum + b)) -----
__global__ void k_gather128(const __half* __restrict__ h, const float* __restrict__ bias,
                            __half* __restrict__ nxt)
{
    int warp = (blockIdx.x * blockDim.x + threadIdx.x) >> 5;
    int lane = threadIdx.x & 31;
    if (warp >= NN) return;
    int beg = g_off[warp], end = g_off[warp + 1];
    const uint2* hp = reinterpret_cast<const uint2*>(h);
    float4 acc = h4_to_f4(hp[warp * 32 + lane]);       // self term
    int i = beg;
    for (; i + 4 <= end; i += 4) {
        float4 v0 = h4_to_f4(hp[g_ep[i    ] * 32 + lane]);
        float4 v1 = h4_to_f4(hp[g_ep[i + 1] * 32 + lane]);
        float4 v2 = h4_to_f4(hp[g_ep[i + 2] * 32 + lane]);
        float4 v3 = h4_to_f4(hp[g_ep[i + 3] * 32 + lane]);
        acc.x += (v0.x + v1.x) + (v2.x + v3.x);
        acc.y += (v0.y + v1.y) + (v2.y + v3.y);
        acc.z += (v0.z + v1.z) + (v2.z + v3.z);
        acc.w += (v0.w + v1.w) + (v2.w + v3.w);
    }
    for (; i < end; i++) {
        float4 v = h4_to_f4(hp[g_ep[i] * 32 + lane]);
        acc.x += v.x; acc.y += v.y; acc.z += v.z; acc.w += v.w;
    }
    float dd = g_dis[warp];
    float4 b = reinterpret_cast<const float4*>(bias)[lane];
    float rx = fmaxf(fmaf(acc.x, dd, b.x), 0.f);
    float ry = fmaxf(fmaf(acc.y, dd, b.y), 0.f);
    float rz = fmaxf(fmaf(acc.z, dd, b.z), 0.f);
    float rw = fmaxf(fmaf(acc.w, dd, b.w), 0.f);
    uint2 o;
    __half2 o0 = __floats2half2_rn(rx, ry);
    __half2 o1 = __floats2half2_rn(rz, rw);
    o.x = *reinterpret_cast<uint32_t*>(&o0);
    o.y = *reinterpret_cast<uint32_t*>(&o1);
    reinterpret_cast<uint2*>(nxt)[warp * 32 + lane] = o;
}

// final layer: COUT=64, fused +b3, fp32 straight to out
__global__ void k_gather64f(const __half* __restrict__ h, const float* __restrict__ b3,
                            float* __restrict__ out)
{
    int warp = (blockIdx.x * blockDim.x + threadIdx.x) >> 5;
    int lane = threadIdx.x & 31;
    if (warp >= NN) return;
    int beg = g_off[warp], end = g_off[warp + 1];
    const uint32_t* hp = reinterpret_cast<const uint32_t*>(h);
    uint32_t su = hp[warp * 32 + lane];
    float2 acc = __half22float2(*reinterpret_cast<__half2*>(&su));  // self term
    int i = beg;
    for (; i + 4 <= end; i += 4) {
        uint32_t u0 = hp[g_ep[i    ] * 32 + lane];
        uint32_t u1 = hp[g_ep[i + 1] * 32 + lane];
        uint32_t u2 = hp[g_ep[i + 2] * 32 + lane];
        uint32_t u3 = hp[g_ep[i + 3] * 32 + lane];
        float2 v0 = __half22float2(*reinterpret_cast<__half2*>(&u0));
        float2 v1 = __half22float2(*reinterpret_cast<__half2*>(&u1));
        float2 v2 = __half22float2(*reinterpret_cast<__half2*>(&u2));
        float2 v3 = __half22float2(*reinterpret_cast<__half2*>(&u3));
        acc.x += (v0.x + v1.x) + (v2.x + v3.x);
        acc.y += (v0.y + v1.y) + (v2.y + v3.y);
    }
    for (; i < end; i++) {
        uint32_t u = hp[g_ep[i] * 32 + lane];
        float2 v = __half22float2(*reinterpret_cast<__half2*>(&u));
        acc.x += v.x; acc.y += v.y;
    }
    float dd = g_dis[warp];
    float2 b = reinterpret_cast<const float2*>(b3)[lane];
    float2 r;
    r.x = fmaf(acc.x, dd, b.x);
    r.y = fmaf(acc.y, dd, b.y);
    reinterpret_cast<float2*>(out)[warp * 32 + lane] = r;
}

// ---------------- launcher ---------------------------------------------------
extern "C" void kernel_launch(void* const* d_in, const int* in_sizes, int n_in,
                              void* d_out, int out_size)
{
    const float* x  = (const float*)d_in[0];
    const int*   ei = (const int*)d_in[1];
    const float* W1 = (const float*)d_in[2];
    const float* b1 = (const float*)d_in[3];
    const float* W2 = (const float*)d_in[4];
    const float* b2 = (const float*)d_in[5];
    const float* W3 = (const float*)d_in[6];
    const float* b3 = (const float*)d_in[7];
    float* out = (float*)d_out;

    const int* src = ei;            // edge_index[0]
    const int* dst = ei + NE;       // edge_index[1]

    __half *ph = nullptr, *pa = nullptr;
    cudaGetSymbolAddress((void**)&ph, g_h);
    cudaGetSymbolAddress((void**)&pa, g_a);
    __half *w1h, *w1l, *w2h, *w2l, *w3h, *w3l;
    cudaGetSymbolAddress((void**)&w1h, g_w1h);
    cudaGetSymbolAddress((void**)&w1l, g_w1l);
    cudaGetSymbolAddress((void**)&w2h, g_w2h);
    cudaGetSymbolAddress((void**)&w2l, g_w2l);
    cudaGetSymbolAddress((void**)&w3h, g_w3h);
    cudaGetSymbolAddress((void**)&w3l, g_w3l);

    const int smemL1 = 2 * 128 * 144 + 2 * 128 * 144;   // 73728 (split A)
    const int smemL2 = 1 * 128 * 144 + 2 * 128 * 144;   // 55296
    const int smemL3 = 1 * 128 * 144 + 2 * 64 * 144;    // 36864
    cudaFuncSetAttribute(k_gemm_mma<128, false>, cudaFuncAttributeMaxDynamicSharedMemorySize, smemL1);
    cudaFuncSetAttribute(k_gemm_mma<128, true>,  cudaFuncAttributeMaxDynamicSharedMemorySize, smemL2);
    cudaFuncSetAttribute(k_gemm_mma<64,  true>,  cudaFuncAttributeMaxDynamicSharedMemorySize, smemL3);

    const int gB = (NN + 127) / 128;         // 782 M-tiles
    const int gG = (NN * 32 + 255) / 256;    // warp per node

    // launch order arranged so gemm1 is the 4th launch (ncu profiles #4)
    k_init<<<NBLK, 256>>>(W1, W2, W3);                                   // 1
    k_deg_count<<<(NE + 255) / 256, 256>>>(dst);                         // 2
    k_scan1<<<NBLK, 256>>>();                                            // 3
    k_gemm_mma<128, false><<<gB, 256, smemL1>>>(x, w1h, w1l, ph);        // 4 <- profiled
    k_scan2<<<1, 512>>>();                                               // 5
    k_scan3<<<NBLK, 256>>>();                                            // 6
    k_fill<<<(NE + 255) / 256, 256>>>(src, dst);                         // 7
    k_gather128<<<gG, 256>>>(ph, b1, pa);                                // 8
    k_gemm_mma<128, true><<<gB, 256, smemL2>>>(pa, w2h, w2l, ph);        // 9
    k_gather128<<<gG, 256>>>(ph, b2, pa);                                // 10
    k_gemm_mma<64, true><<<gB, 256, smemL3>>>(pa, w3h, w3l, ph);         // 11
    k_gather64f<<<gG, 256>>>(ph, b3, out);                               // 12
}

// round 11
// speedup vs baseline: 1.3337x; 1.0407x over previous
#include <cuda_runtime.h>
#include <cuda_fp16.h>
#include <cstdint>

#define NN 100000
#define NE 1600000
#define CIN 128
#define NBLK ((NN + 255) / 256)   // 391 scan blocks

// ---------------- scratch ---------------------------------------------------
static __device__ int    g_deg[NN];
static __device__ int    g_cur[NN];
static __device__ float  g_dis[NN];
static __device__ int    g_off[NN + 1];
static __device__ int    g_bsum[512];
static __device__ int    g_bscan[512];
static __device__ int    g_ep[NE];                 // src per (dst-sorted) edge
static __device__ __half g_h[(size_t)NN * 128];    // UNscaled transform out (fp16)
static __device__ __half g_a[(size_t)NN * 128];    // relu(agg+b) layer input (fp16)
// pre-transposed + fp16 hi/lo split weights: [COUT][CIN]
static __device__ __half g_w1h[128 * 128], g_w1l[128 * 128];
static __device__ __half g_w2h[128 * 128], g_w2l[128 * 128];
static __device__ __half g_w3h[64 * 128],  g_w3l[64 * 128];

// ---------------- PTX helpers ------------------------------------------------
__device__ __forceinline__ void ldsm4(uint32_t* r, uint32_t addr) {
    asm volatile("ldmatrix.sync.aligned.m8n8.x4.shared.b16 {%0,%1,%2,%3}, [%4];"
                 : "=r"(r[0]), "=r"(r[1]), "=r"(r[2]), "=r"(r[3]) : "r"(addr));
}
__device__ __forceinline__ uint32_t smem_u32(const void* p) {
    uint32_t a;
    asm("{ .reg .u64 t; cvta.to.shared.u64 t, %1; cvt.u32.u64 %0, t; }" : "=r"(a) : "l"(p));
    return a;
}
__device__ __forceinline__ void mma16816(float* d, const uint32_t* a,
                                         uint32_t b0, uint32_t b1) {
    asm volatile(
        "mma.sync.aligned.m16n8k16.row.col.f32.f16.f16.f32 "
        "{%0,%1,%2,%3}, {%4,%5,%6,%7}, {%8,%9}, {%0,%1,%2,%3};"
        : "+f"(d[0]), "+f"(d[1]), "+f"(d[2]), "+f"(d[3])
        : "r"(a[0]), "r"(a[1]), "r"(a[2]), "r"(a[3]), "r"(b0), "r"(b1));
}
__device__ __forceinline__ float4 h4_to_f4(uint2 u) {
    float2 a = __half22float2(*reinterpret_cast<__half2*>(&u.x));
    float2 b = __half22float2(*reinterpret_cast<__half2*>(&u.y));
    return make_float4(a.x, a.y, b.x, b.y);
}

// ---------------- init: self-loop degree + weight transpose/split ------------
__global__ void k_init(const float* __restrict__ W1, const float* __restrict__ W2,
                       const float* __restrict__ W3) {
    int i = blockIdx.x * blockDim.x + threadIdx.x;
    if (i < NN) g_deg[i] = 1;                       // self loop
    if (i < 16384) {
        int k = i >> 7, n = i & 127;
        float v = W1[i];
        __half hi = __float2half_rn(v);
        g_w1h[n * 128 + k] = hi;
        g_w1l[n * 128 + k] = __float2half_rn(v - __half2float(hi));
        v = W2[i]; hi = __float2half_rn(v);
        g_w2h[n * 128 + k] = hi;
        g_w2l[n * 128 + k] = __float2half_rn(v - __half2float(hi));
    }
    if (i < 8192) {
        int k = i >> 6, n = i & 63;
        float v = W3[i];
        __half hi = __float2half_rn(v);
        g_w3h[n * 128 + k] = hi;
        g_w3l[n * 128 + k] = __float2half_rn(v - __half2float(hi));
    }
}
__global__ void k_deg_count(const int* __restrict__ dst) {
    int e = blockIdx.x * blockDim.x + threadIdx.x;
    if (e < NE) atomicAdd(&g_deg[dst[e]], 1);
}

// ---------------- CSR build (dis fused into scan1) ---------------------------
__global__ void k_scan1() {
    __shared__ int s[256];
    int t = threadIdx.x;
    int i = blockIdx.x * 256 + t;
    int deg = (i < NN) ? g_deg[i] : 1;
    if (i < NN) g_dis[i] = rsqrtf((float)deg);
    int v = (i < NN) ? (deg - 1) : 0;
    s[t] = v; __syncthreads();
#pragma unroll
    for (int off = 1; off < 256; off <<= 1) {
        int a = (t >= off) ? s[t - off] : 0;
        __syncthreads();
        s[t] += a; __syncthreads();
    }
    if (i < NN) g_off[i] = s[t] - v;
    if (t == 255) g_bsum[blockIdx.x] = s[255];
}
__global__ void k_scan2() {
    __shared__ int s[512];
    int t = threadIdx.x;
    int v = (t < NBLK) ? g_bsum[t] : 0;
    s[t] = v; __syncthreads();
#pragma unroll
    for (int off = 1; off < 512; off <<= 1) {
        int a = (t >= off) ? s[t - off] : 0;
        __syncthreads();
        s[t] += a; __syncthreads();
    }
    g_bscan[t] = s[t] - v;
}
__global__ void k_scan3() {
    int i = blockIdx.x * blockDim.x + threadIdx.x;
    if (i < NN) {
        int o = g_off[i] + g_bscan[i >> 8];
        g_off[i] = o;
        g_cur[i] = o;
    }
    if (i == 0) g_off[NN] = NE;
}
__global__ void k_fill(const int* __restrict__ src, const int* __restrict__ dst) {
    int e = blockIdx.x * blockDim.x + threadIdx.x;
    if (e >= NE) return;
    int pos = atomicAdd(&g_cur[dst[e]], 1);
    g_ep[pos] = src[e];
}

// ---------------- fp16 tensor-core GEMM: h = fp16(in @ W) --------------------
// Weights split w = wh + wl (fp16 each, 22-bit effective). No dis here.
// HALF_IN (layers 2,3): A exact fp16 -> D = A*wh + A*wl.
// fp32 in (layer 1): A split hi/lo fp16 -> D = Ah*wh + Al*wh + Ah*wl.
template <int COUT, bool HALF_IN>
__global__ void __launch_bounds__(256, 2)
k_gemm_mma(const void* __restrict__ in_, const __half* __restrict__ wh,
           const __half* __restrict__ wl, __half* __restrict__ h)
{
    constexpr int PITCH = 144;                 // bytes per smem row (72 halves)
    constexpr int ASZ = 128 * PITCH;           // 18432
    constexpr int BSZ = COUT * PITCH;
    constexpr int NAB = HALF_IN ? 1 : 2;       // A buffers
    constexpr int NTW = COUT / 16;

    extern __shared__ char smem[];
    char* A0 = smem;                           // A (or A_hi)
    char* A1 = smem + ASZ;                     // A_lo (split mode only)
    char* Bh = smem + NAB * ASZ;
    char* Bl = Bh + BSZ;
    uint32_t sb = smem_u32(smem);

    int tid = threadIdx.x;
    int wid = tid >> 5, lane = tid & 31;
    int wm = wid >> 1, wn = wid & 1;
    int row0 = blockIdx.x * 128;

    float acc[2][NTW][4];
#pragma unroll
    for (int f = 0; f < 2; f++)
#pragma unroll
        for (int t = 0; t < NTW; t++)
#pragma unroll
            for (int q = 0; q < 4; q++) acc[f][t][q] = 0.f;

    uint32_t lrow = lane & 7, quad = lane >> 3;
    uint32_t aoff = sb +
                    (wm * 32 + lrow + ((quad & 1) << 3)) * PITCH + ((quad & 2) << 3);
    uint32_t boff = sb + (uint32_t)(NAB * ASZ) +
                    (wn * (COUT / 2) + lrow + ((quad & 2) << 2)) * PITCH + ((quad & 1) << 4);

    for (int c = 0; c < 2; c++) {
        // ---- stage A chunk [128 x 64] --------------------------------------
        {
            int r = tid >> 1, half = tid & 1;
            int gr = row0 + r;
            if (HALF_IN) {
                const uint4* ip = reinterpret_cast<const uint4*>(
                    (const __half*)in_ + (size_t)gr * CIN + c * 64 + half * 32);
                uint4* ar = reinterpret_cast<uint4*>(A0 + r * PITCH + half * 64);
                if (gr < NN) {
#pragma unroll
                    for (int q = 0; q < 4; q++) ar[q] = ip[q];
                } else {
                    uint4 z = make_uint4(0, 0, 0, 0);
#pragma unroll
                    for (int q = 0; q < 4; q++) ar[q] = z;
                }
            } else {
                const float* ip = (const float*)in_ + (size_t)gr * CIN + c * 64 + half * 32;
                __half2* arh = reinterpret_cast<__half2*>(A0 + r * PITCH + half * 64);
                __half2* arl = reinterpret_cast<__half2*>(A1 + r * PITCH + half * 64);
#pragma unroll
                for (int q = 0; q < 8; q++) {
                    float4 v = make_float4(0.f, 0.f, 0.f, 0.f);
                    if (gr < NN) v = *reinterpret_cast<const float4*>(ip + q * 4);
                    __half2 h0 = __floats2half2_rn(v.x, v.y);
                    __half2 h1 = __floats2half2_rn(v.z, v.w);
                    __half2 l0 = __floats2half2_rn(v.x - __low2float(h0),
                                                   v.y - __high2float(h0));
                    __half2 l1 = __floats2half2_rn(v.z - __low2float(h1),
                                                   v.w - __high2float(h1));
                    arh[q * 2] = h0; arh[q * 2 + 1] = h1;
                    arl[q * 2] = l0; arl[q * 2 + 1] = l1;
                }
            }
        }
        // ---- stage B chunk [COUT x 64] fp16 copy ---------------------------
        {
            constexpr int TPR = 256 / COUT;
            constexpr int VPT = 8 / TPR;
            int n = tid / TPR, part = tid % TPR;
            const uint4* sh = reinterpret_cast<const uint4*>(wh + n * 128 + c * 64) + part * VPT;
            const uint4* sl = reinterpret_cast<const uint4*>(wl + n * 128 + c * 64) + part * VPT;
            uint4* dh = reinterpret_cast<uint4*>(Bh + n * PITCH) + part * VPT;
            uint4* dl = reinterpret_cast<uint4*>(Bl + n * PITCH) + part * VPT;
#pragma unroll
            for (int v = 0; v < VPT; v++) { dh[v] = sh[v]; dl[v] = sl[v]; }
        }
        __syncthreads();

        // ---- compute: 4 k16 steps ------------------------------------------
#pragma unroll
        for (int kk = 0; kk < 4; kk++) {
            uint32_t ka = (uint32_t)(kk << 5);
            uint32_t afr[2][4], afl[2][4];
            ldsm4(afr[0], aoff + ka);
            ldsm4(afr[1], aoff + 16 * PITCH + ka);
            if (!HALF_IN) {
                ldsm4(afl[0], aoff + ASZ + ka);
                ldsm4(afl[1], aoff + ASZ + 16 * PITCH + ka);
            }
#pragma unroll
            for (int tp = 0; tp < NTW / 2; tp++) {
                uint32_t bfr[4], bfl[4];
                ldsm4(bfr, boff + tp * 16 * PITCH + ka);
                ldsm4(bfl, boff + BSZ + tp * 16 * PITCH + ka);
#pragma unroll
                for (int f = 0; f < 2; f++) {
                    mma16816(acc[f][2 * tp],     afr[f], bfr[0], bfr[1]);
                    mma16816(acc[f][2 * tp],     afr[f], bfl[0], bfl[1]);
                    mma16816(acc[f][2 * tp + 1], afr[f], bfr[2], bfr[3]);
                    mma16816(acc[f][2 * tp + 1], afr[f], bfl[2], bfl[3]);
                    if (!HALF_IN) {
                        mma16816(acc[f][2 * tp],     afl[f], bfr[0], bfr[1]);
                        mma16816(acc[f][2 * tp + 1], afl[f], bfr[2], bfr[3]);
                    }
                }
            }
        }
        __syncthreads();
    }

    // ---- epilogue: store h as fp16 (no dis scaling) -------------------------
#pragma unroll
    for (int f = 0; f < 2; f++) {
        int r0g = row0 + wm * 32 + f * 16 + (lane >> 2);
#pragma unroll
        for (int t = 0; t < NTW; t++) {
            int ncol = wn * (COUT / 2) + t * 8 + ((lane & 3) << 1);
            if (r0g < NN) {
                __half2 o = __floats2half2_rn(acc[f][t][0], acc[f][t][1]);
                *reinterpret_cast<__half2*>(h + (size_t)r0g * COUT + ncol) = o;
            }
            if (r0g + 8 < NN) {
                __half2 o = __floats2half2_rn(acc[f][t][2], acc[f][t][3]);
                *reinterpret_cast<__half2*>(h + (size_t)(r0g + 8) * COUT + ncol) = o;
            }
        }
    }
}

// --------- gather (layers 1,2): nxt = fp16(relu(dd*(Σ dis[s]h[s] + dd*h[d]) + b))
__global__ void k_gather128(const __half* __restrict__ h, const float* __restrict__ bias,
                            __half* __restrict__ nxt)
{
    int warp = (blockIdx.x * blockDim.x + threadIdx.x) >> 5;
    int lane = threadIdx.x & 31;
    if (warp >= NN) return;
    int beg = g_off[warp], end = g_off[warp + 1];
    float dd = g_dis[warp];
    const uint2* hp = reinterpret_cast<const uint2*>(h);
    float4 sv = h4_to_f4(hp[warp * 32 + lane]);
    float4 acc = make_float4(sv.x * dd, sv.y * dd, sv.z * dd, sv.w * dd);  // self
    int i = beg;
    for (; i + 4 <= end; i += 4) {
        int s0 = g_ep[i], s1 = g_ep[i + 1], s2 = g_ep[i + 2], s3 = g_ep[i + 3];
        float w0 = g_dis[s0], w1 = g_dis[s1], w2 = g_dis[s2], w3 = g_dis[s3];
        float4 v0 = h4_to_f4(hp[s0 * 32 + lane]);
        float4 v1 = h4_to_f4(hp[s1 * 32 + lane]);
        float4 v2 = h4_to_f4(hp[s2 * 32 + lane]);
        float4 v3 = h4_to_f4(hp[s3 * 32 + lane]);
        acc.x = fmaf(w0, v0.x, fmaf(w1, v1.x, fmaf(w2, v2.x, fmaf(w3, v3.x, acc.x))));
        acc.y = fmaf(w0, v0.y, fmaf(w1, v1.y, fmaf(w2, v2.y, fmaf(w3, v3.y, acc.y))));
        acc.z = fmaf(w0, v0.z, fmaf(w1, v1.z, fmaf(w2, v2.z, fmaf(w3, v3.z, acc.z))));
        acc.w = fmaf(w0, v0.w, fmaf(w1, v1.w, fmaf(w2, v2.w, fmaf(w3, v3.w, acc.w))));
    }
    for (; i < end; i++) {
        int s = g_ep[i];
        float w = g_dis[s];
        float4 v = h4_to_f4(hp[s * 32 + lane]);
        acc.x = fmaf(w, v.x, acc.x); acc.y = fmaf(w, v.y, acc.y);
        acc.z = fmaf(w, v.z, acc.z); acc.w = fmaf(w, v.w, acc.w);
    }
    float4 b = reinterpret_cast<const float4*>(bias)[lane];
    float rx = fmaxf(fmaf(acc.x, dd, b.x), 0.f);
    float ry = fmaxf(fmaf(acc.y, dd, b.y), 0.f);
    float rz = fmaxf(fmaf(acc.z, dd, b.z), 0.f);
    float rw = fmaxf(fmaf(acc.w, dd, b.w), 0.f);
    uint2 o;
    __half2 o0 = __floats2half2_rn(rx, ry);
    __half2 o1 = __floats2half2_rn(rz, rw);
    o.x = *reinterpret_cast<uint32_t*>(&o0);
    o.y = *reinterpret_cast<uint32_t*>(&o1);
    reinterpret_cast<uint2*>(nxt)[warp * 32 + lane] = o;
}

// final layer: COUT=64, fused +b3, fp32 straight to out
__global__ void k_gather64f(const __half* __restrict__ h, const float* __restrict__ b3,
                            float* __restrict__ out)
{
    int warp = (blockIdx.x * blockDim.x + threadIdx.x) >> 5;
    int lane = threadIdx.x & 31;
    if (warp >= NN) return;
    int beg = g_off[warp], end = g_off[warp + 1];
    float dd = g_dis[warp];
    const uint32_t* hp = reinterpret_cast<const uint32_t*>(h);
    uint32_t su = hp[warp * 32 + lane];
    float2 sv = __half22float2(*reinterpret_cast<__half2*>(&su));
    float2 acc = make_float2(sv.x * dd, sv.y * dd);    // self
    int i = beg;
    for (; i + 4 <= end; i += 4) {
        int s0 = g_ep[i], s1 = g_ep[i + 1], s2 = g_ep[i + 2], s3 = g_ep[i + 3];
        float w0 = g_dis[s0], w1 = g_dis[s1], w2 = g_dis[s2], w3 = g_dis[s3];
        uint32_t u0 = hp[s0 * 32 + lane], u1 = hp[s1 * 32 + lane];
        uint32_t u2 = hp[s2 * 32 + lane], u3 = hp[s3 * 32 + lane];
        float2 v0 = __half22float2(*reinterpret_cast<__half2*>(&u0));
        float2 v1 = __half22float2(*reinterpret_cast<__half2*>(&u1));
        float2 v2 = __half22float2(*reinterpret_cast<__half2*>(&u2));
        float2 v3 = __half22float2(*reinterpret_cast<__half2*>(&u3));
        acc.x = fmaf(w0, v0.x, fmaf(w1, v1.x, fmaf(w2, v2.x, fmaf(w3, v3.x, acc.x))));
        acc.y = fmaf(w0, v0.y, fmaf(w1, v1.y, fmaf(w2, v2.y, fmaf(w3, v3.y, acc.y))));
    }
    for (; i < end; i++) {
        int s = g_ep[i];
        float w = g_dis[s];
        uint32_t u = hp[s * 32 + lane];
        float2 v = __half22float2(*reinterpret_cast<__half2*>(&u));
        acc.x = fmaf(w, v.x, acc.x); acc.y = fmaf(w, v.y, acc.y);
    }
    float2 b = reinterpret_cast<const float2*>(b3)[lane];
    float2 r;
    r.x = fmaf(acc.x, dd, b.x);
    r.y = fmaf(acc.y, dd, b.y);
    reinterpret_cast<float2*>(out)[warp * 32 + lane] = r;
}

// ---------------- launcher ---------------------------------------------------
extern "C" void kernel_launch(void* const* d_in, const int* in_sizes, int n_in,
                              void* d_out, int out_size)
{
    const float* x  = (const float*)d_in[0];
    const int*   ei = (const int*)d_in[1];
    const float* W1 = (const float*)d_in[2];
    const float* b1 = (const float*)d_in[3];
    const float* W2 = (const float*)d_in[4];
    const float* b2 = (const float*)d_in[5];
    const float* W3 = (const float*)d_in[6];
    const float* b3 = (const float*)d_in[7];
    float* out = (float*)d_out;

    const int* src = ei;            // edge_index[0]
    const int* dst = ei + NE;       // edge_index[1]

    __half *ph = nullptr, *pa = nullptr;
    cudaGetSymbolAddress((void**)&ph, g_h);
    cudaGetSymbolAddress((void**)&pa, g_a);
    __half *w1h, *w1l, *w2h, *w2l, *w3h, *w3l;
    cudaGetSymbolAddress((void**)&w1h, g_w1h);
    cudaGetSymbolAddress((void**)&w1l, g_w1l);
    cudaGetSymbolAddress((void**)&w2h, g_w2h);
    cudaGetSymbolAddress((void**)&w2l, g_w2l);
    cudaGetSymbolAddress((void**)&w3h, g_w3h);
    cudaGetSymbolAddress((void**)&w3l, g_w3l);

    const int smemL1 = 2 * 128 * 144 + 2 * 128 * 144;   // 73728 (split A)
    const int smemL2 = 1 * 128 * 144 + 2 * 128 * 144;   // 55296
    const int smemL3 = 1 * 128 * 144 + 2 * 64 * 144;    // 36864
    cudaFuncSetAttribute(k_gemm_mma<128, false>, cudaFuncAttributeMaxDynamicSharedMemorySize, smemL1);
    cudaFuncSetAttribute(k_gemm_mma<128, true>,  cudaFuncAttributeMaxDynamicSharedMemorySize, smemL2);
    cudaFuncSetAttribute(k_gemm_mma<64,  true>,  cudaFuncAttributeMaxDynamicSharedMemorySize, smemL3);

    const int gB = (NN + 127) / 128;         // 782 M-tiles
    const int gG = (NN * 32 + 255) / 256;    // warp per node

    // fork machinery (host objects only; safe during stream capture)
    cudaStream_t s2;
    cudaStreamCreateWithFlags(&s2, cudaStreamNonBlocking);
    cudaEvent_t eFork, eJoin;
    cudaEventCreateWithFlags(&eFork, cudaEventDisableTiming);
    cudaEventCreateWithFlags(&eJoin, cudaEventDisableTiming);

    // ---- setup root ----
    k_init<<<NBLK, 256>>>(W1, W2, W3);
    cudaEventRecord(eFork, 0);

    // ---- branch A (side stream): layer-1 GEMM (needs only weights) ----
    cudaStreamWaitEvent(s2, eFork, 0);
    k_gemm_mma<128, false><<<gB, 256, smemL1, s2>>>(x, w1h, w1l, ph);
    cudaEventRecord(eJoin, s2);

    // ---- branch B (main stream): CSR build ----
    k_deg_count<<<(NE + 255) / 256, 256>>>(dst);
    k_scan1<<<NBLK, 256>>>();
    k_scan2<<<1, 512>>>();
    k_scan3<<<NBLK, 256>>>();
    k_fill<<<(NE + 255) / 256, 256>>>(src, dst);

    // ---- join, then serial layer chain ----
    cudaStreamWaitEvent(0, eJoin, 0);
    k_gather128<<<gG, 256>>>(ph, b1, pa);
    k_gemm_mma<128, true><<<gB, 256, smemL2>>>(pa, w2h, w2l, ph);
    k_gather128<<<gG, 256>>>(ph, b2, pa);
    k_gemm_mma<64, true><<<gB, 256, smemL3>>>(pa, w3h, w3l, ph);
    k_gather64f<<<gG, 256>>>(ph, b3, out);
    // streams/events intentionally not destroyed: they are host-side objects
    // (no device memory) and destroying mid-capture is unsafe.
}

// round 12
// speedup vs baseline: 1.3806x; 1.0352x over previous
#include <cuda_runtime.h>
#include <cuda_fp16.h>
#include <cstdint>

#define NN 100000
#define NE 1600000
#define CIN 128
#define NBLK ((NN + 255) / 256)   // 391 scan blocks

// ---------------- scratch ---------------------------------------------------
static __device__ int    g_deg[NN];
static __device__ int    g_cur[NN];
static __device__ float  g_dis[NN];
static __device__ int    g_off[NN + 1];
static __device__ int    g_bsum[512];
static __device__ int    g_bscan[512];
static __device__ int    g_ep[NE];                 // src per (dst-sorted) edge
static __device__ __half g_h[(size_t)NN * 128];    // dis-scaled messages (fp16)
static __device__ __half g_a[(size_t)NN * 128];    // relu(agg+b) layer input (fp16)
// pre-transposed + fp16 hi/lo split weights: [COUT][CIN]
static __device__ __half g_w1h[128 * 128], g_w1l[128 * 128];
static __device__ __half g_w2h[128 * 128], g_w2l[128 * 128];
static __device__ __half g_w3h[64 * 128],  g_w3l[64 * 128];

// ---------------- PTX helpers ------------------------------------------------
__device__ __forceinline__ void ldsm4(uint32_t* r, uint32_t addr) {
    asm volatile("ldmatrix.sync.aligned.m8n8.x4.shared.b16 {%0,%1,%2,%3}, [%4];"
                 : "=r"(r[0]), "=r"(r[1]), "=r"(r[2]), "=r"(r[3]) : "r"(addr));
}
__device__ __forceinline__ uint32_t smem_u32(const void* p) {
    uint32_t a;
    asm("{ .reg .u64 t; cvta.to.shared.u64 t, %1; cvt.u32.u64 %0, t; }" : "=r"(a) : "l"(p));
    return a;
}
__device__ __forceinline__ void mma16816(float* d, const uint32_t* a,
                                         uint32_t b0, uint32_t b1) {
    asm volatile(
        "mma.sync.aligned.m16n8k16.row.col.f32.f16.f16.f32 "
        "{%0,%1,%2,%3}, {%4,%5,%6,%7}, {%8,%9}, {%0,%1,%2,%3};"
        : "+f"(d[0]), "+f"(d[1]), "+f"(d[2]), "+f"(d[3])
        : "r"(a[0]), "r"(a[1]), "r"(a[2]), "r"(a[3]), "r"(b0), "r"(b1));
}
__device__ __forceinline__ float4 h4_to_f4(uint2 u) {
    float2 a = __half22float2(*reinterpret_cast<__half2*>(&u.x));
    float2 b = __half22float2(*reinterpret_cast<__half2*>(&u.y));
    return make_float4(a.x, a.y, b.x, b.y);
}

// ---------------- init: self-loop degree + weight transpose/split ------------
__global__ void k_init(const float* __restrict__ W1, const float* __restrict__ W2,
                       const float* __restrict__ W3) {
    int i = blockIdx.x * blockDim.x + threadIdx.x;
    if (i < NN) g_deg[i] = 1;                       // self loop
    if (i < 16384) {
        int k = i >> 7, n = i & 127;
        float v = W1[i];
        __half hi = __float2half_rn(v);
        g_w1h[n * 128 + k] = hi;
        g_w1l[n * 128 + k] = __float2half_rn(v - __half2float(hi));
        v = W2[i]; hi = __float2half_rn(v);
        g_w2h[n * 128 + k] = hi;
        g_w2l[n * 128 + k] = __float2half_rn(v - __half2float(hi));
    }
    if (i < 8192) {
        int k = i >> 6, n = i & 63;
        float v = W3[i];
        __half hi = __float2half_rn(v);
        g_w3h[n * 128 + k] = hi;
        g_w3l[n * 128 + k] = __float2half_rn(v - __half2float(hi));
    }
}
__global__ void k_deg_count(const int* __restrict__ dst) {
    int e = blockIdx.x * blockDim.x + threadIdx.x;
    if (e < NE) atomicAdd(&g_deg[dst[e]], 1);
}

// ---------------- CSR build (dis fused into scan1) ---------------------------
__global__ void k_scan1() {
    __shared__ int s[256];
    int t = threadIdx.x;
    int i = blockIdx.x * 256 + t;
    int deg = (i < NN) ? g_deg[i] : 1;
    if (i < NN) g_dis[i] = rsqrtf((float)deg);
    int v = (i < NN) ? (deg - 1) : 0;
    s[t] = v; __syncthreads();
#pragma unroll
    for (int off = 1; off < 256; off <<= 1) {
        int a = (t >= off) ? s[t - off] : 0;
        __syncthreads();
        s[t] += a; __syncthreads();
    }
    if (i < NN) g_off[i] = s[t] - v;
    if (t == 255) g_bsum[blockIdx.x] = s[255];
}
__global__ void k_scan2() {
    __shared__ int s[512];
    int t = threadIdx.x;
    int v = (t < NBLK) ? g_bsum[t] : 0;
    s[t] = v; __syncthreads();
#pragma unroll
    for (int off = 1; off < 512; off <<= 1) {
        int a = (t >= off) ? s[t - off] : 0;
        __syncthreads();
        s[t] += a; __syncthreads();
    }
    g_bscan[t] = s[t] - v;
}
__global__ void k_scan3() {
    int i = blockIdx.x * blockDim.x + threadIdx.x;
    if (i < NN) {
        int o = g_off[i] + g_bscan[i >> 8];
        g_off[i] = o;
        g_cur[i] = o;
    }
    if (i == 0) g_off[NN] = NE;
}
__global__ void k_fill(const int* __restrict__ src, const int* __restrict__ dst) {
    int e = blockIdx.x * blockDim.x + threadIdx.x;
    if (e >= NE) return;
    int pos = atomicAdd(&g_cur[dst[e]], 1);
    g_ep[pos] = src[e];
}

// ---------------- scale layer-1 messages: h *= dis[row] (in place) -----------
// runs on the side stream after dis is ready; hidden under scan2/scan3/fill
__global__ void k_scale() {
    int idx = blockIdx.x * blockDim.x + threadIdx.x;     // uint2 = 4 halves
    if (idx >= NN * 32) return;
    int row = idx >> 5;
    float dd = g_dis[row];
    uint2* hp = reinterpret_cast<uint2*>(g_h);
    float4 v = h4_to_f4(hp[idx]);
    __half2 o0 = __floats2half2_rn(v.x * dd, v.y * dd);
    __half2 o1 = __floats2half2_rn(v.z * dd, v.w * dd);
    uint2 o;
    o.x = *reinterpret_cast<uint32_t*>(&o0);
    o.y = *reinterpret_cast<uint32_t*>(&o1);
    hp[idx] = o;
}

// ---------------- fp16 tensor-core GEMM --------------------------------------
// Weights split w = wh + wl (fp16 each, 22-bit effective).
// HALF_IN (layers 2,3): A exact fp16 -> D = A*wh + A*wl; epilogue scales by dis.
// fp32 in (layer 1): A split hi/lo -> 3 MMAs; epilogue stores UNscaled
// (dis applied later by k_scale, so gemm1 has no CSR dependency).
template <int COUT, bool HALF_IN>
__global__ void __launch_bounds__(256, 2)
k_gemm_mma(const void* __restrict__ in_, const __half* __restrict__ wh,
           const __half* __restrict__ wl, __half* __restrict__ h)
{
    constexpr int PITCH = 144;                 // bytes per smem row (72 halves)
    constexpr int ASZ = 128 * PITCH;           // 18432
    constexpr int BSZ = COUT * PITCH;
    constexpr int NAB = HALF_IN ? 1 : 2;       // A buffers
    constexpr int NTW = COUT / 16;

    extern __shared__ char smem[];
    char* A0 = smem;                           // A (or A_hi)
    char* A1 = smem + ASZ;                     // A_lo (split mode only)
    char* Bh = smem + NAB * ASZ;
    char* Bl = Bh + BSZ;
    uint32_t sb = smem_u32(smem);

    int tid = threadIdx.x;
    int wid = tid >> 5, lane = tid & 31;
    int wm = wid >> 1, wn = wid & 1;
    int row0 = blockIdx.x * 128;

    float acc[2][NTW][4];
#pragma unroll
    for (int f = 0; f < 2; f++)
#pragma unroll
        for (int t = 0; t < NTW; t++)
#pragma unroll
            for (int q = 0; q < 4; q++) acc[f][t][q] = 0.f;

    uint32_t lrow = lane & 7, quad = lane >> 3;
    uint32_t aoff = sb +
                    (wm * 32 + lrow + ((quad & 1) << 3)) * PITCH + ((quad & 2) << 3);
    uint32_t boff = sb + (uint32_t)(NAB * ASZ) +
                    (wn * (COUT / 2) + lrow + ((quad & 2) << 2)) * PITCH + ((quad & 1) << 4);

    for (int c = 0; c < 2; c++) {
        // ---- stage A chunk [128 x 64] --------------------------------------
        {
            int r = tid >> 1, half = tid & 1;
            int gr = row0 + r;
            if (HALF_IN) {
                const uint4* ip = reinterpret_cast<const uint4*>(
                    (const __half*)in_ + (size_t)gr * CIN + c * 64 + half * 32);
                uint4* ar = reinterpret_cast<uint4*>(A0 + r * PITCH + half * 64);
                if (gr < NN) {
#pragma unroll
                    for (int q = 0; q < 4; q++) ar[q] = ip[q];
                } else {
                    uint4 z = make_uint4(0, 0, 0, 0);
#pragma unroll
                    for (int q = 0; q < 4; q++) ar[q] = z;
                }
            } else {
                const float* ip = (const float*)in_ + (size_t)gr * CIN + c * 64 + half * 32;
                __half2* arh = reinterpret_cast<__half2*>(A0 + r * PITCH + half * 64);
                __half2* arl = reinterpret_cast<__half2*>(A1 + r * PITCH + half * 64);
#pragma unroll
                for (int q = 0; q < 8; q++) {
                    float4 v = make_float4(0.f, 0.f, 0.f, 0.f);
                    if (gr < NN) v = *reinterpret_cast<const float4*>(ip + q * 4);
                    __half2 h0 = __floats2half2_rn(v.x, v.y);
                    __half2 h1 = __floats2half2_rn(v.z, v.w);
                    __half2 l0 = __floats2half2_rn(v.x - __low2float(h0),
                                                   v.y - __high2float(h0));
                    __half2 l1 = __floats2half2_rn(v.z - __low2float(h1),
                                                   v.w - __high2float(h1));
                    arh[q * 2] = h0; arh[q * 2 + 1] = h1;
                    arl[q * 2] = l0; arl[q * 2 + 1] = l1;
                }
            }
        }
        // ---- stage B chunk [COUT x 64] fp16 copy ---------------------------
        {
            constexpr int TPR = 256 / COUT;
            constexpr int VPT = 8 / TPR;
            int n = tid / TPR, part = tid % TPR;
            const uint4* sh = reinterpret_cast<const uint4*>(wh + n * 128 + c * 64) + part * VPT;
            const uint4* sl = reinterpret_cast<const uint4*>(wl + n * 128 + c * 64) + part * VPT;
            uint4* dh = reinterpret_cast<uint4*>(Bh + n * PITCH) + part * VPT;
            uint4* dl = reinterpret_cast<uint4*>(Bl + n * PITCH) + part * VPT;
#pragma unroll
            for (int v = 0; v < VPT; v++) { dh[v] = sh[v]; dl[v] = sl[v]; }
        }
        __syncthreads();

        // ---- compute: 4 k16 steps ------------------------------------------
#pragma unroll
        for (int kk = 0; kk < 4; kk++) {
            uint32_t ka = (uint32_t)(kk << 5);
            uint32_t afr[2][4], afl[2][4];
            ldsm4(afr[0], aoff + ka);
            ldsm4(afr[1], aoff + 16 * PITCH + ka);
            if (!HALF_IN) {
                ldsm4(afl[0], aoff + ASZ + ka);
                ldsm4(afl[1], aoff + ASZ + 16 * PITCH + ka);
            }
#pragma unroll
            for (int tp = 0; tp < NTW / 2; tp++) {
                uint32_t bfr[4], bfl[4];
                ldsm4(bfr, boff + tp * 16 * PITCH + ka);
                ldsm4(bfl, boff + BSZ + tp * 16 * PITCH + ka);
#pragma unroll
                for (int f = 0; f < 2; f++) {
                    mma16816(acc[f][2 * tp],     afr[f], bfr[0], bfr[1]);
                    mma16816(acc[f][2 * tp],     afr[f], bfl[0], bfl[1]);
                    mma16816(acc[f][2 * tp + 1], afr[f], bfr[2], bfr[3]);
                    mma16816(acc[f][2 * tp + 1], afr[f], bfl[2], bfl[3]);
                    if (!HALF_IN) {
                        mma16816(acc[f][2 * tp],     afl[f], bfr[0], bfr[1]);
                        mma16816(acc[f][2 * tp + 1], afl[f], bfr[2], bfr[3]);
                    }
                }
            }
        }
        __syncthreads();
    }

    // ---- epilogue -----------------------------------------------------------
#pragma unroll
    for (int f = 0; f < 2; f++) {
        int r0g = row0 + wm * 32 + f * 16 + (lane >> 2);
        float ds0 = 1.f, ds1 = 1.f;
        if (HALF_IN) {
            ds0 = (r0g < NN) ? g_dis[r0g] : 0.f;
            ds1 = (r0g + 8 < NN) ? g_dis[r0g + 8] : 0.f;
        }
#pragma unroll
        for (int t = 0; t < NTW; t++) {
            int ncol = wn * (COUT / 2) + t * 8 + ((lane & 3) << 1);
            if (r0g < NN) {
                __half2 o = __floats2half2_rn(acc[f][t][0] * ds0, acc[f][t][1] * ds0);
                *reinterpret_cast<__half2*>(h + (size_t)r0g * COUT + ncol) = o;
            }
            if (r0g + 8 < NN) {
                __half2 o = __floats2half2_rn(acc[f][t][2] * ds1, acc[f][t][3] * ds1);
                *reinterpret_cast<__half2*>(h + (size_t)(r0g + 8) * COUT + ncol) = o;
            }
        }
    }
}

// --------- gather (layers 1,2): nxt = fp16(relu(dd*(Σ h'[s] + h'[d]) + b)) ---
__global__ void k_gather128(const __half* __restrict__ h, const float* __restrict__ bias,
                            __half* __restrict__ nxt)
{
    int warp = (blockIdx.x * blockDim.x + threadIdx.x) >> 5;
    int lane = threadIdx.x & 31;
    if (warp >= NN) return;
    int beg = g_off[warp], end = g_off[warp + 1];
    const uint2* hp = reinterpret_cast<const uint2*>(h);
    float4 acc = h4_to_f4(hp[warp * 32 + lane]);       // self term
    int i = beg;
    for (; i + 4 <= end; i += 4) {
        float4 v0 = h4_to_f4(hp[g_ep[i    ] * 32 + lane]);
        float4 v1 = h4_to_f4(hp[g_ep[i + 1] * 32 + lane]);
        float4 v2 = h4_to_f4(hp[g_ep[i + 2] * 32 + lane]);
        float4 v3 = h4_to_f4(hp[g_ep[i + 3] * 32 + lane]);
        acc.x += (v0.x + v1.x) + (v2.x + v3.x);
        acc.y += (v0.y + v1.y) + (v2.y + v3.y);
        acc.z += (v0.z + v1.z) + (v2.z + v3.z);
        acc.w += (v0.w + v1.w) + (v2.w + v3.w);
    }
    for (; i < end; i++) {
        float4 v = h4_to_f4(hp[g_ep[i] * 32 + lane]);
        acc.x += v.x; acc.y += v.y; acc.z += v.z; acc.w += v.w;
    }
    float dd = g_dis[warp];
    float4 b = reinterpret_cast<const float4*>(bias)[lane];
    float rx = fmaxf(fmaf(acc.x, dd, b.x), 0.f);
    float ry = fmaxf(fmaf(acc.y, dd, b.y), 0.f);
    float rz = fmaxf(fmaf(acc.z, dd, b.z), 0.f);
    float rw = fmaxf(fmaf(acc.w, dd, b.w), 0.f);
    uint2 o;
    __half2 o0 = __floats2half2_rn(rx, ry);
    __half2 o1 = __floats2half2_rn(rz, rw);
    o.x = *reinterpret_cast<uint32_t*>(&o0);
    o.y = *reinterpret_cast<uint32_t*>(&o1);
    reinterpret_cast<uint2*>(nxt)[warp * 32 + lane] = o;
}

// final layer: COUT=64, fused +b3, fp32 straight to out
__global__ void k_gather64f(const __half* __restrict__ h, const float* __restrict__ b3,
                            float* __restrict__ out)
{
    int warp = (blockIdx.x * blockDim.x + threadIdx.x) >> 5;
    int lane = threadIdx.x & 31;
    if (warp >= NN) return;
    int beg = g_off[warp], end = g_off[warp + 1];
    const uint32_t* hp = reinterpret_cast<const uint32_t*>(h);
    uint32_t su = hp[warp * 32 + lane];
    float2 acc = __half22float2(*reinterpret_cast<__half2*>(&su));  // self term
    int i = beg;
    for (; i + 4 <= end; i += 4) {
        uint32_t u0 = hp[g_ep[i    ] * 32 + lane];
        uint32_t u1 = hp[g_ep[i + 1] * 32 + lane];
        uint32_t u2 = hp[g_ep[i + 2] * 32 + lane];
        uint32_t u3 = hp[g_ep[i + 3] * 32 + lane];
        float2 v0 = __half22float2(*reinterpret_cast<__half2*>(&u0));
        float2 v1 = __half22float2(*reinterpret_cast<__half2*>(&u1));
        float2 v2 = __half22float2(*reinterpret_cast<__half2*>(&u2));
        float2 v3 = __half22float2(*reinterpret_cast<__half2*>(&u3));
        acc.x += (v0.x + v1.x) + (v2.x + v3.x);
        acc.y += (v0.y + v1.y) + (v2.y + v3.y);
    }
    for (; i < end; i++) {
        uint32_t u = hp[g_ep[i] * 32 + lane];
        float2 v = __half22float2(*reinterpret_cast<__half2*>(&u));
        acc.x += v.x; acc.y += v.y;
    }
    float dd = g_dis[warp];
    float2 b = reinterpret_cast<const float2*>(b3)[lane];
    float2 r;
    r.x = fmaf(acc.x, dd, b.x);
    r.y = fmaf(acc.y, dd, b.y);
    reinterpret_cast<float2*>(out)[warp * 32 + lane] = r;
}

// ---------------- launcher ---------------------------------------------------
extern "C" void kernel_launch(void* const* d_in, const int* in_sizes, int n_in,
                              void* d_out, int out_size)
{
    const float* x  = (const float*)d_in[0];
    const int*   ei = (const int*)d_in[1];
    const float* W1 = (const float*)d_in[2];
    const float* b1 = (const float*)d_in[3];
    const float* W2 = (const float*)d_in[4];
    const float* b2 = (const float*)d_in[5];
    const float* W3 = (const float*)d_in[6];
    const float* b3 = (const float*)d_in[7];
    float* out = (float*)d_out;

    const int* src = ei;            // edge_index[0]
    const int* dst = ei + NE;       // edge_index[1]

    __half *ph = nullptr, *pa = nullptr;
    cudaGetSymbolAddress((void**)&ph, g_h);
    cudaGetSymbolAddress((void**)&pa, g_a);
    __half *w1h, *w1l, *w2h, *w2l, *w3h, *w3l;
    cudaGetSymbolAddress((void**)&w1h, g_w1h);
    cudaGetSymbolAddress((void**)&w1l, g_w1l);
    cudaGetSymbolAddress((void**)&w2h, g_w2h);
    cudaGetSymbolAddress((void**)&w2l, g_w2l);
    cudaGetSymbolAddress((void**)&w3h, g_w3h);
    cudaGetSymbolAddress((void**)&w3l, g_w3l);

    const int smemL1 = 2 * 128 * 144 + 2 * 128 * 144;   // 73728 (split A)
    const int smemL2 = 1 * 128 * 144 + 2 * 128 * 144;   // 55296
    const int smemL3 = 1 * 128 * 144 + 2 * 64 * 144;    // 36864
    cudaFuncSetAttribute(k_gemm_mma<128, false>, cudaFuncAttributeMaxDynamicSharedMemorySize, smemL1);
    cudaFuncSetAttribute(k_gemm_mma<128, true>,  cudaFuncAttributeMaxDynamicSharedMemorySize, smemL2);
    cudaFuncSetAttribute(k_gemm_mma<64,  true>,  cudaFuncAttributeMaxDynamicSharedMemorySize, smemL3);

    const int gB = (NN + 127) / 128;         // 782 M-tiles
    const int gG = (NN * 32 + 255) / 256;    // warp per node

    // fork machinery (host objects only; safe during stream capture)
    cudaStream_t s2;
    cudaStreamCreateWithFlags(&s2, cudaStreamNonBlocking);
    cudaEvent_t eFork, eDis, eJoin;
    cudaEventCreateWithFlags(&eFork, cudaEventDisableTiming);
    cudaEventCreateWithFlags(&eDis,  cudaEventDisableTiming);
    cudaEventCreateWithFlags(&eJoin, cudaEventDisableTiming);

    // ---- setup root ----
    k_init<<<NBLK, 256>>>(W1, W2, W3);
    cudaEventRecord(eFork, 0);

    // ---- branch A (side stream): layer-1 GEMM (weights only) ----
    cudaStreamWaitEvent(s2, eFork, 0);
    k_gemm_mma<128, false><<<gB, 256, smemL1, s2>>>(x, w1h, w1l, ph);

    // ---- branch B (main stream): degree + dis ----
    k_deg_count<<<(NE + 255) / 256, 256>>>(dst);
    k_scan1<<<NBLK, 256>>>();
    cudaEventRecord(eDis, 0);                       // dis ready

    // side stream: scale h1 by dis once available (hidden under scan2..fill)
    cudaStreamWaitEvent(s2, eDis, 0);
    k_scale<<<(NN * 32 + 255) / 256, 256, 0, s2>>>();
    cudaEventRecord(eJoin, s2);

    // main stream: finish CSR
    k_scan2<<<1, 512>>>();
    k_scan3<<<NBLK, 256>>>();
    k_fill<<<(NE + 255) / 256, 256>>>(src, dst);

    // ---- join, then serial layer chain ----
    cudaStreamWaitEvent(0, eJoin, 0);
    k_gather128<<<gG, 256>>>(ph, b1, pa);
    k_gemm_mma<128, true><<<gB, 256, smemL2>>>(pa, w2h, w2l, ph);
    k_gather128<<<gG, 256>>>(ph, b2, pa);
    k_gemm_mma<64, true><<<gB, 256, smemL3>>>(pa, w3h, w3l, ph);
    k_gather64f<<<gG, 256>>>(ph, b3, out);
    // streams/events intentionally not destroyed (host objects; capture-safe)
}